// round 13
// baseline (speedup 1.0000x reference)
#include <cuda_runtime.h>
#include <cuda_bf16.h>
#include <cstdint>

// B=2, C=512, N=4096. out = x + Wo@Attn(GN(x)) + bo, [B,C,H,W] fp32.
// Value-side fold: W' = Wo Wv, b2 = Wo bv  ->  out = x + (W'h+b2)@P^T/Z + bo.
// Score path as R11: q,k with s*log2e folded; P~ = exp2(q.k); Z = rowsum.
#define BATCH 2
#define CCH   512
#define NPIX  4096
#define NQK   1024
#define GEPS  1e-6f

static const long long CN  = (long long)CCH * NPIX;   // 2M
static const long long NN  = (long long)NPIX * NPIX;  // 16M
static const long long QKN = (long long)NPIX * NQK;   // 4M

// scratch (device globals)
__device__ __nv_bfloat16 g_ht [BATCH * NPIX * CCH];             // hT [B][pix][C]
__device__ __nv_bfloat16 g_qk [(long long)BATCH * NPIX * NQK];  // [B][pix][q|k]
__device__ __nv_bfloat16 g_vv [BATCH * CCH * NPIX];             // vv [B][C][pix]
__device__ __nv_bfloat16 g_p  [(long long)BATCH * NPIX * NPIX]; // exp scores bf16
__device__ __nv_bfloat16 g_wqk[NQK * CCH];                      // concat(wq*qs, wk)
__device__ __nv_bfloat16 g_Wp [CCH * CCH];                      // W' = Wo Wv
__device__ float         g_bqk[NQK];                            // concat(bq*qs, bk)
__device__ float         g_b2 [CCH];                            // Wo bv
__device__ float         g_rowsum[BATCH * NPIX];
__device__ float         g_ssum4[BATCH * 32 * 4 * 2];           // GN partials

// ---------------------------------------------------------------------------
// PTX helpers
// ---------------------------------------------------------------------------
__device__ __forceinline__ void cpasync16(uint32_t s, const void* g) {
    asm volatile("cp.async.cg.shared.global [%0], [%1], 16;" :: "r"(s), "l"(g));
}
__device__ __forceinline__ uint32_t smem_u32(const void* p) {
    return (uint32_t)__cvta_generic_to_shared(p);
}
__device__ __forceinline__ void ldsm4(uint32_t r[4], uint32_t addr) {
    asm volatile("ldmatrix.sync.aligned.m8n8.x4.shared.b16 {%0,%1,%2,%3}, [%4];"
        : "=r"(r[0]), "=r"(r[1]), "=r"(r[2]), "=r"(r[3]) : "r"(addr));
}
__device__ __forceinline__ void mma_bf16(float c[4], const uint32_t a[4],
                                         const uint32_t b0, const uint32_t b1) {
    asm volatile(
        "mma.sync.aligned.m16n8k16.row.col.f32.bf16.bf16.f32 "
        "{%0,%1,%2,%3},{%4,%5,%6,%7},{%8,%9},{%0,%1,%2,%3};"
        : "+f"(c[0]), "+f"(c[1]), "+f"(c[2]), "+f"(c[3])
        : "r"(a[0]), "r"(a[1]), "r"(a[2]), "r"(a[3]), "r"(b0), "r"(b1));
}
__device__ __forceinline__ float ex2f(float x) {
    float y; asm("ex2.approx.ftz.f32 %0, %1;" : "=f"(y) : "f"(x));
    return y;
}

// ---------------------------------------------------------------------------
// bf16 tensor-core GEMM: D[M][N] = A[M][K] * B[N][K]^T (both K-major rows)
// Block 128x128x64, 256 thr = 8 warps (2x4), warp tile 64x32, m16n8k16,
// 3-stage cp.async, 2 CTAs/SM. (R8/R10/R11 proven-best mainloop.)
// EPI 1: bf16 out + bias[n]                              (qk)
// EPI 5: bf16 out + bias[m]                              (vv)
// EPI 2: exp2(acc) bf16 + rowsum atomics (per-row m)     (S)
// EPI 3: fp32 out = acc/rs[col] + bias[m] + res_x        (AV = final)
// ---------------------------------------------------------------------------
#define BM 128
#define BN 128
#define BK 64
#define ASTR 144
#define ASTAGE (BM * ASTR)
#define BSTAGE (BN * ASTR)
#define SMEM3 (3 * (ASTAGE + BSTAGE))   // 110592

template<int EPI>
__global__ __launch_bounds__(256, 2) void gemm_bf16_tc(
    const __nv_bfloat16* __restrict__ A, const __nv_bfloat16* __restrict__ B,
    void* __restrict__ Cv,
    const float* __restrict__ bias, const float* __restrict__ aux,
    const float* __restrict__ res,
    int K, int lda, int ldb, int ldc,
    long long sA, long long sB, long long sC, long long sAux, long long sR)
{
    extern __shared__ char smem[];
    const uint32_t sbA = smem_u32(smem);
    const uint32_t sbB = sbA + 3 * ASTAGE;

    const int tid  = threadIdx.x;
    const int wid  = tid >> 5;
    const int lane = tid & 31;
    const int g    = lane >> 2;
    const int tig  = lane & 3;
    const int sub  = lane >> 3;
    const int r8   = lane & 7;
    const int m_w  = (wid >> 2) * 64;
    const int n_w  = (wid & 3) * 32;
    const int m0   = blockIdx.y * BM;
    const int n0   = blockIdx.x * BN;
    const int z    = blockIdx.z;

    const __nv_bfloat16* Ab = A + (long long)z * sA + (long long)m0 * lda;
    const __nv_bfloat16* Bb = B + (long long)z * sB + (long long)n0 * ldb;

    float acc[4][4][4];
    #pragma unroll
    for (int i = 0; i < 4; i++)
        #pragma unroll
        for (int j = 0; j < 4; j++)
            #pragma unroll
            for (int r = 0; r < 4; r++) acc[i][j][r] = 0.f;

    const int nk = K / BK;

    auto load = [&](int ks, int buf) {
        const uint32_t ab = sbA + buf * ASTAGE;
        const uint32_t bb = sbB + buf * BSTAGE;
        #pragma unroll
        for (int it = 0; it < 4; it++) {
            int s = tid + it * 256;
            int r = s >> 3, c = s & 7;
            cpasync16(ab + r * ASTR + c * 16,
                      Ab + (long long)r * lda + ks * BK + c * 8);
        }
        #pragma unroll
        for (int it = 0; it < 4; it++) {
            int s = tid + it * 256;
            int r = s >> 3, c = s & 7;
            cpasync16(bb + r * ASTR + c * 16,
                      Bb + (long long)r * ldb + ks * BK + c * 8);
        }
        asm volatile("cp.async.commit_group;");
    };

    load(0, 0);
    if (nk > 1) load(1, 1);

    #pragma unroll 1
    for (int ks = 0; ks < nk; ks++) {
        const int buf = ks % 3;
        if (ks + 1 < nk) asm volatile("cp.async.wait_group 1;");
        else             asm volatile("cp.async.wait_group 0;");
        __syncthreads();
        if (ks + 2 < nk) load(ks + 2, (ks + 2) % 3);

        const uint32_t ab = sbA + buf * ASTAGE;
        const uint32_t bb = sbB + buf * BSTAGE;

        #pragma unroll
        for (int kk = 0; kk < 4; kk++) {
            uint32_t af[4][4];
            #pragma unroll
            for (int i = 0; i < 4; i++) {
                uint32_t addr = ab + (m_w + 16 * i + (sub & 1) * 8 + r8) * ASTR
                              + kk * 32 + (sub >> 1) * 16;
                ldsm4(af[i], addr);
            }
            uint32_t bf[4][2];
            #pragma unroll
            for (int jj = 0; jj < 2; jj++) {
                uint32_t t[4];
                uint32_t addr = bb + (n_w + 16 * jj + (sub >> 1) * 8 + r8) * ASTR
                              + kk * 32 + (sub & 1) * 16;
                ldsm4(t, addr);
                bf[2 * jj][0] = t[0]; bf[2 * jj][1] = t[1];
                bf[2 * jj + 1][0] = t[2]; bf[2 * jj + 1][1] = t[3];
            }
            #pragma unroll
            for (int i = 0; i < 4; i++)
                #pragma unroll
                for (int j = 0; j < 4; j++)
                    mma_bf16(acc[i][j], af[i], bf[j][0], bf[j][1]);
        }
    }

    // ------------------------------ epilogues ------------------------------
    if (EPI == 1) {           // bf16 + bias[n]
        __nv_bfloat16* C = (__nv_bfloat16*)Cv + (long long)z * sC;
        #pragma unroll
        for (int i = 0; i < 4; i++) {
            int r0 = m0 + m_w + 16 * i + g, r1 = r0 + 8;
            #pragma unroll
            for (int j = 0; j < 4; j++) {
                int col = n0 + n_w + 8 * j + 2 * tig;
                float bn0 = bias[col], bn1 = bias[col + 1];
                *(__nv_bfloat162*)&C[(long long)r0 * ldc + col] =
                    __float22bfloat162_rn(make_float2(acc[i][j][0] + bn0,
                                                      acc[i][j][1] + bn1));
                *(__nv_bfloat162*)&C[(long long)r1 * ldc + col] =
                    __float22bfloat162_rn(make_float2(acc[i][j][2] + bn0,
                                                      acc[i][j][3] + bn1));
            }
        }
    } else if (EPI == 5) {    // bf16 + bias[m]
        __nv_bfloat16* C = (__nv_bfloat16*)Cv + (long long)z * sC;
        #pragma unroll
        for (int i = 0; i < 4; i++) {
            int r0 = m0 + m_w + 16 * i + g, r1 = r0 + 8;
            float bm0 = bias[r0], bm1 = bias[r1];
            #pragma unroll
            for (int j = 0; j < 4; j++) {
                int col = n0 + n_w + 8 * j + 2 * tig;
                *(__nv_bfloat162*)&C[(long long)r0 * ldc + col] =
                    __float22bfloat162_rn(make_float2(acc[i][j][0] + bm0,
                                                      acc[i][j][1] + bm0));
                *(__nv_bfloat162*)&C[(long long)r1 * ldc + col] =
                    __float22bfloat162_rn(make_float2(acc[i][j][2] + bm1,
                                                      acc[i][j][3] + bm1));
            }
        }
    } else if (EPI == 2) {    // exp2, bf16 out, rowsum atomics (per-row m)
        __nv_bfloat16* C = (__nv_bfloat16*)Cv + (long long)z * sC;
        float* rs = (float*)aux + (long long)z * sAux;
        #pragma unroll
        for (int i = 0; i < 4; i++) {
            int r0 = m0 + m_w + 16 * i + g, r1 = r0 + 8;
            float s0 = 0.f, s1 = 0.f;
            #pragma unroll
            for (int j = 0; j < 4; j++) {
                int col = n0 + n_w + 8 * j + 2 * tig;
                float e0 = ex2f(acc[i][j][0]);
                float e1 = ex2f(acc[i][j][1]);
                float e2 = ex2f(acc[i][j][2]);
                float e3 = ex2f(acc[i][j][3]);
                s0 += e0 + e1; s1 += e2 + e3;
                *(__nv_bfloat162*)&C[(long long)r0 * ldc + col] =
                    __float22bfloat162_rn(make_float2(e0, e1));
                *(__nv_bfloat162*)&C[(long long)r1 * ldc + col] =
                    __float22bfloat162_rn(make_float2(e2, e3));
            }
            s0 += __shfl_xor_sync(0xffffffffu, s0, 1);
            s0 += __shfl_xor_sync(0xffffffffu, s0, 2);
            s1 += __shfl_xor_sync(0xffffffffu, s1, 1);
            s1 += __shfl_xor_sync(0xffffffffu, s1, 2);
            if (tig == 0) {
                atomicAdd(&rs[r0], s0);
                atomicAdd(&rs[r1], s1);
            }
        }
    } else {                  // EPI 3: fp32 = acc/rs[col] + bias[m] + x
        float* C = (float*)Cv + (long long)z * sC;
        const float* rs = aux + (long long)z * sAux;
        const float* xr = res + (long long)z * sR;
        #pragma unroll
        for (int j = 0; j < 4; j++) {          // j outer: hoist reciprocals
            int col = n0 + n_w + 8 * j + 2 * tig;
            float i0 = 1.f / rs[col], i1 = 1.f / rs[col + 1];
            #pragma unroll
            for (int i = 0; i < 4; i++) {
                int r0 = m0 + m_w + 16 * i + g, r1 = r0 + 8;
                float bm0 = bias[r0], bm1 = bias[r1];
                long long o0 = (long long)r0 * ldc + col;
                long long o1 = (long long)r1 * ldc + col;
                float2 x0 = *(const float2*)&xr[o0];
                float2 x1 = *(const float2*)&xr[o1];
                float2 v0 = make_float2(acc[i][j][0] * i0 + bm0 + x0.x,
                                        acc[i][j][1] * i1 + bm0 + x0.y);
                float2 v1 = make_float2(acc[i][j][2] * i0 + bm1 + x1.x,
                                        acc[i][j][3] * i1 + bm1 + x1.y);
                *(float2*)&C[o0] = v0;
                *(float2*)&C[o1] = v1;
            }
        }
    }
}

// ---------------------------------------------------------------------------
// Fused prologue:
//  [0,2048)       qk weight prep (wq*qs | wk -> bf16; bias fold)
//  [2048,2304)    W' = Wo Wv fold (bf16)
//  [2304,2306)    b2 = Wo bv
//  [2306,2562)    GN partial stats
//  [2562,2594)    zero rowsum
// ---------------------------------------------------------------------------
#define PQ0 0
#define PW0 2048
#define PB0 2304
#define PS0 2306
#define PZ0 2562
#define PRO_BLOCKS 2594

__global__ __launch_bounds__(256) void prologue_kernel(
    const float* __restrict__ x,
    const float* __restrict__ wq, const float* __restrict__ wk,
    const float* __restrict__ wv, const float* __restrict__ wo,
    const float* __restrict__ bq, const float* __restrict__ bk,
    const float* __restrict__ bv,
    __nv_bfloat16* __restrict__ wqk, __nv_bfloat16* __restrict__ Wp,
    float* __restrict__ bqk, float* __restrict__ b2,
    float* __restrict__ ssum4, float* __restrict__ rowsum)
{
    const int blk = blockIdx.x;
    const int t = threadIdx.x;
    const float qs = 0.044194173824159216f * 1.4426950408889634f;  // s*lg2e

    if (blk < PW0) {
        int idx = blk * 256 + t;               // 0 .. 1024*512-1
        int row = idx >> 9, col = idx & 511;
        int which = row >> 9, rr = row & 511;
        float v = which == 0 ? wq[rr * 512 + col] * qs : wk[rr * 512 + col];
        wqk[idx] = __float2bfloat16_rn(v);
        if (idx < NQK) {
            int w2 = idx >> 9, r2 = idx & 511;
            bqk[idx] = w2 == 0 ? bq[r2] * qs : bk[r2];
        }
    } else if (blk < PB0) {
        // W'[c][c'] = sum_co wo[c][co] * wv[co][c']
        const int tb = blk - PW0;
        const int cb  = (tb >> 4) * 32;
        const int cpb = (tb & 15) * 32;
        __shared__ float sa[32][33], sv[32][33];
        float a00 = 0, a01 = 0, a10 = 0, a11 = 0;
        const int a = (t >> 4) * 2, b = (t & 15) * 2;
        for (int co0 = 0; co0 < 512; co0 += 32) {
            #pragma unroll
            for (int it = 0; it < 4; it++) {
                int idx = t + it * 256; int r = idx >> 5, cc = idx & 31;
                sa[r][cc] = wo[(cb + r) * 512 + co0 + cc];
                sv[r][cc] = wv[(co0 + r) * 512 + cpb + cc];
            }
            __syncthreads();
            #pragma unroll 8
            for (int r = 0; r < 32; r++) {
                float o0 = sa[a][r], o1 = sa[a + 1][r];
                float v0 = sv[r][b], v1 = sv[r][b + 1];
                a00 += o0 * v0; a01 += o0 * v1;
                a10 += o1 * v0; a11 += o1 * v1;
            }
            __syncthreads();
        }
        Wp[(cb + a) * 512 + cpb + b]         = __float2bfloat16_rn(a00);
        Wp[(cb + a) * 512 + cpb + b + 1]     = __float2bfloat16_rn(a01);
        Wp[(cb + a + 1) * 512 + cpb + b]     = __float2bfloat16_rn(a10);
        Wp[(cb + a + 1) * 512 + cpb + b + 1] = __float2bfloat16_rn(a11);
    } else if (blk < PS0) {
        int c = (blk - PB0) * 256 + t;
        float s = 0.f;
        for (int co = 0; co < 512; co++) s += wo[c * 512 + co] * bv[co];
        b2[c] = s;
    } else if (blk < PZ0) {
        const int pb = blk - PS0;
        const long long base = (long long)(pb >> 2) * 65536 + (pb & 3) * 16384;
        float s = 0.f, ss = 0.f;
        #pragma unroll 4
        for (int i = t; i < 16384; i += 256) {
            float v = x[base + i];
            s += v; ss += v * v;
        }
        #pragma unroll
        for (int off = 16; off; off >>= 1) {
            s  += __shfl_down_sync(0xffffffffu, s,  off);
            ss += __shfl_down_sync(0xffffffffu, ss, off);
        }
        __shared__ float shs[8], shss[8];
        int wid = t >> 5, lane = t & 31;
        if (lane == 0) { shs[wid] = s; shss[wid] = ss; }
        __syncthreads();
        if (t == 0) {
            float ts = 0.f, tss = 0.f;
            #pragma unroll
            for (int i = 0; i < 8; i++) { ts += shs[i]; tss += shss[i]; }
            ssum4[2 * pb]     = ts;
            ssum4[2 * pb + 1] = tss;
        }
    } else {
        int idx = (blk - PZ0) * 256 + t;
        rowsum[idx] = 0.f;
    }
}

// ---------------------------------------------------------------------------
// GN apply + transpose (bf16 out); sums 4 stat partials inline (as R11)
// ---------------------------------------------------------------------------
__global__ __launch_bounds__(256) void gn_apply_t_kernel(
    const float* __restrict__ x, const float* __restrict__ w,
    const float* __restrict__ b, const float* __restrict__ ssum4,
    __nv_bfloat16* __restrict__ ht)
{
    __shared__ float tile[32][33];
    const int p0 = blockIdx.x * 32;
    const int c0 = blockIdx.y * 32;
    const int bb = blockIdx.z;
    const int tx = threadIdx.x, ty = threadIdx.y;   // (32, 8)
    const long long xb = (long long)bb * CN;

    #pragma unroll
    for (int r = 0; r < 4; r++) {
        int cl = ty + 8 * r;
        tile[cl][tx] = x[xb + (long long)(c0 + cl) * NPIX + p0 + tx];
    }
    __syncthreads();
    const int c = c0 + tx;
    const int gidx = c >> 4;
    const int bg = bb * 32 + gidx;
    float ts = 0.f, tss = 0.f;
    #pragma unroll
    for (int pp = 0; pp < 4; pp++) {
        ts  += ssum4[2 * (bg * 4 + pp)];
        tss += ssum4[2 * (bg * 4 + pp) + 1];
    }
    const float mean = ts * (1.f / 65536.f);
    const float var  = tss * (1.f / 65536.f) - mean * mean;
    const float rstd = rsqrtf(var + GEPS);
    const float sc = rstd * w[c];
    const float sh = b[c] - mean * sc;
    #pragma unroll
    for (int r = 0; r < 4; r++) {
        int pl = ty + 8 * r;
        float v = tile[tx][pl] * sc + sh;
        ht[xb + (long long)(p0 + pl) * CCH + c] = __float2bfloat16_rn(v);
    }
}

// ---------------------------------------------------------------------------
extern "C" void kernel_launch(void* const* d_in, const int* in_sizes, int n_in,
                              void* d_out, int out_size)
{
    const float* x    = (const float*)d_in[0];
    const float* gn_w = (const float*)d_in[1];
    const float* gn_b = (const float*)d_in[2];
    const float* wq   = (const float*)d_in[3];
    const float* bq   = (const float*)d_in[4];
    const float* wk   = (const float*)d_in[5];
    const float* bk   = (const float*)d_in[6];
    const float* wv   = (const float*)d_in[7];
    const float* bv   = (const float*)d_in[8];
    const float* wo   = (const float*)d_in[9];
    const float* bo   = (const float*)d_in[10];
    float* out = (float*)d_out;

    __nv_bfloat16 *ht, *qk, *vv, *p, *wqk, *Wp;
    float *bqk, *b2, *rowsum, *ssum4;
    cudaGetSymbolAddress((void**)&ht,     g_ht);
    cudaGetSymbolAddress((void**)&qk,     g_qk);
    cudaGetSymbolAddress((void**)&vv,     g_vv);
    cudaGetSymbolAddress((void**)&p,      g_p);
    cudaGetSymbolAddress((void**)&wqk,    g_wqk);
    cudaGetSymbolAddress((void**)&Wp,     g_Wp);
    cudaGetSymbolAddress((void**)&bqk,    g_bqk);
    cudaGetSymbolAddress((void**)&b2,     g_b2);
    cudaGetSymbolAddress((void**)&rowsum, g_rowsum);
    cudaGetSymbolAddress((void**)&ssum4,  g_ssum4);

    cudaFuncSetAttribute(gemm_bf16_tc<1>,
        cudaFuncAttributeMaxDynamicSharedMemorySize, SMEM3);
    cudaFuncSetAttribute(gemm_bf16_tc<5>,
        cudaFuncAttributeMaxDynamicSharedMemorySize, SMEM3);
    cudaFuncSetAttribute(gemm_bf16_tc<2>,
        cudaFuncAttributeMaxDynamicSharedMemorySize, SMEM3);
    cudaFuncSetAttribute(gemm_bf16_tc<3>,
        cudaFuncAttributeMaxDynamicSharedMemorySize, SMEM3);

    // 0) prologue: weight prep + W' fold + b2 + GN stats + rowsum zero
    prologue_kernel<<<PRO_BLOCKS, 256>>>(
        x, wq, wk, wv, wo, bq, bk, bv, wqk, Wp, bqk, b2, ssum4, rowsum);

    // 1) GN apply + transpose -> hT bf16 [B][pix][C]
    gn_apply_t_kernel<<<dim3(NPIX / 32, CCH / 32, BATCH), dim3(32, 8)>>>(
        x, gn_w, gn_b, ssum4, ht);

    // 2) qk[pix][1024] = ht @ wqk^T + bqk[n]
    dim3 gQK(NQK / BN, NPIX / BM, BATCH);        // (8, 32, 2)
    gemm_bf16_tc<1><<<gQK, 256, SMEM3>>>(
        ht, wqk, qk, bqk, nullptr, nullptr,
        CCH, CCH, CCH, NQK, CN, 0, QKN, 0, 0);

    // 3) vv[C][pix] = W' @ ht^T + b2[m]
    dim3 gV(NPIX / BN, CCH / BM, BATCH);         // (32, 4, 2)
    gemm_bf16_tc<5><<<gV, 256, SMEM3>>>(
        Wp, ht, vv, b2, nullptr, nullptr,
        CCH, CCH, CCH, NPIX, 0, CN, CN, 0, 0);

    // 4) P~ = exp2(q @ k^T) -> bf16, rowsum accumulated
    dim3 gS(NPIX / BN, NPIX / BM, BATCH);        // (32, 32, 2)
    gemm_bf16_tc<2><<<gS, 256, SMEM3>>>(
        qk, qk + 512, p, nullptr, rowsum, nullptr,
        CCH, NQK, NQK, NPIX, QKN, QKN, NN, NPIX, 0);

    // 5) out = x + (vv @ P~^T)/rowsum[col] + bo[m]  (M=512, N=4096, K=4096)
    dim3 gAV(NPIX / BN, CCH / BM, BATCH);        // (32, 4, 2)
    gemm_bf16_tc<3><<<gAV, 256, SMEM3>>>(
        vv, p, out, bo, rowsum, x,
        NPIX, NPIX, NPIX, NPIX, CN, NN, CN, NPIX, CN);
}

// round 14
// speedup vs baseline: 1.2064x; 1.2064x over previous
#include <cuda_runtime.h>
#include <cuda_bf16.h>
#include <cstdint>

// B=2, C=512, N=4096. out = x + Wo@Attn(GN(x)) + bo, [B,C,H,W] fp32.
#define BATCH 2
#define CCH   512
#define NPIX  4096
#define NQKV  1536
#define GEPS  1e-6f

static const long long CN   = (long long)CCH * NPIX;    // 2M
static const long long NN   = (long long)NPIX * NPIX;   // 16M
static const long long QKVN = (long long)NPIX * NQKV;   // 6M

// scratch (device globals)
__device__ __nv_bfloat16 g_ht [BATCH * NPIX * CCH];             // hT [B][pix][C]
__device__ __nv_bfloat16 g_qkv[(long long)BATCH * NPIX * NQKV]; // [B][pix][q|k|v]
__device__ __nv_bfloat16 g_p  [(long long)BATCH * NPIX * NPIX]; // exp(S) bf16
__device__ __nv_bfloat16 g_ot [BATCH * NPIX * CCH];             // OT [B][pix][C]
__device__ __nv_bfloat16 g_wqkv[NQKV * CCH];                    // concat(wq*s*lg2e,wk,wv)
__device__ __nv_bfloat16 g_wo [CCH * CCH];
__device__ float         g_bqkv[NQKV];
__device__ float         g_rowsum[BATCH * NPIX];                // softmax denominators
__device__ float         g_ssum4[BATCH * 32 * 4 * 2];           // GN partial (sum,sumsq)

// ---------------------------------------------------------------------------
// PTX helpers
// ---------------------------------------------------------------------------
__device__ __forceinline__ void cpasync16(uint32_t s, const void* g) {
    asm volatile("cp.async.cg.shared.global [%0], [%1], 16;" :: "r"(s), "l"(g));
}
__device__ __forceinline__ uint32_t smem_u32(const void* p) {
    return (uint32_t)__cvta_generic_to_shared(p);
}
__device__ __forceinline__ void ldsm4(uint32_t r[4], uint32_t addr) {
    asm volatile("ldmatrix.sync.aligned.m8n8.x4.shared.b16 {%0,%1,%2,%3}, [%4];"
        : "=r"(r[0]), "=r"(r[1]), "=r"(r[2]), "=r"(r[3]) : "r"(addr));
}
__device__ __forceinline__ void ldsm4t(uint32_t r[4], uint32_t addr) {
    asm volatile("ldmatrix.sync.aligned.m8n8.x4.trans.shared.b16 {%0,%1,%2,%3}, [%4];"
        : "=r"(r[0]), "=r"(r[1]), "=r"(r[2]), "=r"(r[3]) : "r"(addr));
}
__device__ __forceinline__ void mma_bf16(float c[4], const uint32_t a[4],
                                         const uint32_t b0, const uint32_t b1) {
    asm volatile(
        "mma.sync.aligned.m16n8k16.row.col.f32.bf16.bf16.f32 "
        "{%0,%1,%2,%3},{%4,%5,%6,%7},{%8,%9},{%0,%1,%2,%3};"
        : "+f"(c[0]), "+f"(c[1]), "+f"(c[2]), "+f"(c[3])
        : "r"(a[0]), "r"(a[1]), "r"(a[2]), "r"(a[3]), "r"(b0), "r"(b1));
}
__device__ __forceinline__ float ex2f(float x) {
    float y; asm("ex2.approx.ftz.f32 %0, %1;" : "=f"(y) : "f"(x));
    return y;
}

// ---------------------------------------------------------------------------
// bf16 tensor-core GEMM (proven-best config): D[M][N] = A[M][K] * B^T
//   A bf16 [M][K]; TRB=0: B bf16 [N][K]; TRB=1: B bf16 [K][N] (ldmatrix.trans)
// Block 128x128x64, 256 thr = 8 warps (2x4), warp tile 64x32, m16n8k16,
// 3-stage cp.async, 2 CTAs/SM.
// EPI: 1 = bf16 out + bias[n]
//      2 = exp2 + bf16 out + rowsum atomics (aux=rowsum, stride sAux)
//      3 = bf16 out * (1/rowsum[m])
//      4 = fp32 out + bias[m] + residual
// ---------------------------------------------------------------------------
#define BM 128
#define BN 128
#define BK 64
#define ASTR 144
#define BSTR_N 144
#define BSTR_T 272
#define ASTAGE (BM * ASTR)
#define BSTAGE_N (BN * BSTR_N)
#define BSTAGE_T (BK * BSTR_T)
#define SMEM3_NT (3 * (ASTAGE + BSTAGE_N))   // 110592
#define SMEM3_TR (3 * (ASTAGE + BSTAGE_T))   // 107520

template<int EPI, bool TRB>
__global__ __launch_bounds__(256, 2) void gemm_bf16_tc(
    const __nv_bfloat16* __restrict__ A, const __nv_bfloat16* __restrict__ B,
    void* __restrict__ Cv,
    const float* __restrict__ aux, const float* __restrict__ res,
    int K, int lda, int ldb, int ldc,
    long long sA, long long sB, long long sC, long long sAux, long long sR)
{
    extern __shared__ char smem[];
    constexpr int BSTAGE = TRB ? BSTAGE_T : BSTAGE_N;
    const uint32_t sbA = smem_u32(smem);
    const uint32_t sbB = sbA + 3 * ASTAGE;

    const int tid  = threadIdx.x;
    const int wid  = tid >> 5;
    const int lane = tid & 31;
    const int g    = lane >> 2;
    const int tig  = lane & 3;
    const int sub  = lane >> 3;
    const int r8   = lane & 7;
    const int m_w  = (wid >> 2) * 64;
    const int n_w  = (wid & 3) * 32;
    const int m0   = blockIdx.y * BM;
    const int n0   = blockIdx.x * BN;
    const int z    = blockIdx.z;

    const __nv_bfloat16* Ab = A + (long long)z * sA + (long long)m0 * lda;
    const __nv_bfloat16* Bb = TRB ? (B + (long long)z * sB + n0)
                                  : (B + (long long)z * sB + (long long)n0 * ldb);

    float acc[4][4][4];
    #pragma unroll
    for (int i = 0; i < 4; i++)
        #pragma unroll
        for (int j = 0; j < 4; j++)
            #pragma unroll
            for (int r = 0; r < 4; r++) acc[i][j][r] = 0.f;

    const int nk = K / BK;

    auto load = [&](int ks, int buf) {
        const uint32_t ab = sbA + buf * ASTAGE;
        const uint32_t bb = sbB + buf * BSTAGE;
        #pragma unroll
        for (int it = 0; it < 4; it++) {
            int s = tid + it * 256;
            int r = s >> 3, c = s & 7;
            cpasync16(ab + r * ASTR + c * 16,
                      Ab + (long long)r * lda + ks * BK + c * 8);
        }
        if (!TRB) {
            #pragma unroll
            for (int it = 0; it < 4; it++) {
                int s = tid + it * 256;
                int r = s >> 3, c = s & 7;
                cpasync16(bb + r * BSTR_N + c * 16,
                          Bb + (long long)r * ldb + ks * BK + c * 8);
            }
        } else {
            #pragma unroll
            for (int it = 0; it < 4; it++) {
                int s = tid + it * 256;
                int r = s >> 4, c = s & 15;
                cpasync16(bb + r * BSTR_T + c * 16,
                          Bb + (long long)(ks * BK + r) * ldb + c * 8);
            }
        }
        asm volatile("cp.async.commit_group;");
    };

    load(0, 0);
    if (nk > 1) load(1, 1);

    #pragma unroll 1
    for (int ks = 0; ks < nk; ks++) {
        const int buf = ks % 3;
        if (ks + 1 < nk) asm volatile("cp.async.wait_group 1;");
        else             asm volatile("cp.async.wait_group 0;");
        __syncthreads();
        if (ks + 2 < nk) load(ks + 2, (ks + 2) % 3);

        const uint32_t ab = sbA + buf * ASTAGE;
        const uint32_t bb = sbB + buf * BSTAGE;

        #pragma unroll
        for (int kk = 0; kk < 4; kk++) {
            uint32_t af[4][4];
            #pragma unroll
            for (int i = 0; i < 4; i++) {
                uint32_t addr = ab + (m_w + 16 * i + (sub & 1) * 8 + r8) * ASTR
                              + kk * 32 + (sub >> 1) * 16;
                ldsm4(af[i], addr);
            }
            uint32_t bf[4][2];
            #pragma unroll
            for (int jj = 0; jj < 2; jj++) {
                uint32_t t[4];
                if (!TRB) {
                    uint32_t addr = bb + (n_w + 16 * jj + (sub >> 1) * 8 + r8) * BSTR_N
                                  + kk * 32 + (sub & 1) * 16;
                    ldsm4(t, addr);
                } else {
                    uint32_t addr = bb + (kk * 16 + (sub & 1) * 8 + r8) * BSTR_T
                                  + (n_w + 16 * jj + (sub >> 1) * 8) * 2;
                    ldsm4t(t, addr);
                }
                bf[2 * jj][0] = t[0]; bf[2 * jj][1] = t[1];
                bf[2 * jj + 1][0] = t[2]; bf[2 * jj + 1][1] = t[3];
            }
            #pragma unroll
            for (int i = 0; i < 4; i++)
                #pragma unroll
                for (int j = 0; j < 4; j++)
                    mma_bf16(acc[i][j], af[i], bf[j][0], bf[j][1]);
        }
    }

    // ------------------------------ epilogues ------------------------------
    if (EPI == 1) {           // bf16 out + bias[n]
        __nv_bfloat16* C = (__nv_bfloat16*)Cv + (long long)z * sC;
        #pragma unroll
        for (int i = 0; i < 4; i++) {
            int r0 = m0 + m_w + 16 * i + g, r1 = r0 + 8;
            #pragma unroll
            for (int j = 0; j < 4; j++) {
                int col = n0 + n_w + 8 * j + 2 * tig;
                float bn0 = aux[col], bn1 = aux[col + 1];
                *(__nv_bfloat162*)&C[(long long)r0 * ldc + col] =
                    __float22bfloat162_rn(make_float2(acc[i][j][0] + bn0,
                                                      acc[i][j][1] + bn1));
                *(__nv_bfloat162*)&C[(long long)r1 * ldc + col] =
                    __float22bfloat162_rn(make_float2(acc[i][j][2] + bn0,
                                                      acc[i][j][3] + bn1));
            }
        }
    } else if (EPI == 2) {    // exp2, bf16 out, rowsum atomics
        __nv_bfloat16* C = (__nv_bfloat16*)Cv + (long long)z * sC;
        float* rs = (float*)aux + (long long)z * sAux;
        #pragma unroll
        for (int i = 0; i < 4; i++) {
            int r0 = m0 + m_w + 16 * i + g, r1 = r0 + 8;
            float s0 = 0.f, s1 = 0.f;
            #pragma unroll
            for (int j = 0; j < 4; j++) {
                int col = n0 + n_w + 8 * j + 2 * tig;
                float e0 = ex2f(acc[i][j][0]);
                float e1 = ex2f(acc[i][j][1]);
                float e2 = ex2f(acc[i][j][2]);
                float e3 = ex2f(acc[i][j][3]);
                s0 += e0 + e1; s1 += e2 + e3;
                *(__nv_bfloat162*)&C[(long long)r0 * ldc + col] =
                    __float22bfloat162_rn(make_float2(e0, e1));
                *(__nv_bfloat162*)&C[(long long)r1 * ldc + col] =
                    __float22bfloat162_rn(make_float2(e2, e3));
            }
            s0 += __shfl_xor_sync(0xffffffffu, s0, 1);
            s0 += __shfl_xor_sync(0xffffffffu, s0, 2);
            s1 += __shfl_xor_sync(0xffffffffu, s1, 1);
            s1 += __shfl_xor_sync(0xffffffffu, s1, 2);
            if (tig == 0) {
                atomicAdd(&rs[r0], s0);
                atomicAdd(&rs[r1], s1);
            }
        }
    } else if (EPI == 3) {    // bf16 out scaled by 1/rowsum[m]
        __nv_bfloat16* C = (__nv_bfloat16*)Cv + (long long)z * sC;
        const float* rs = aux + (long long)z * sAux;
        #pragma unroll
        for (int i = 0; i < 4; i++) {
            int r0 = m0 + m_w + 16 * i + g, r1 = r0 + 8;
            float i0 = 1.f / rs[r0];
            float i1 = 1.f / rs[r1];
            #pragma unroll
            for (int j = 0; j < 4; j++) {
                int col = n0 + n_w + 8 * j + 2 * tig;
                *(__nv_bfloat162*)&C[(long long)r0 * ldc + col] =
                    __float22bfloat162_rn(make_float2(acc[i][j][0] * i0,
                                                      acc[i][j][1] * i0));
                *(__nv_bfloat162*)&C[(long long)r1 * ldc + col] =
                    __float22bfloat162_rn(make_float2(acc[i][j][2] * i1,
                                                      acc[i][j][3] * i1));
            }
        }
    } else {                  // EPI == 4: fp32 out + bias[m] + residual
        float* C = (float*)Cv + (long long)z * sC;
        const float* Rb = res + (long long)z * sR;
        #pragma unroll
        for (int i = 0; i < 4; i++) {
            int r0 = m0 + m_w + 16 * i + g, r1 = r0 + 8;
            float bm0 = aux[r0], bm1 = aux[r1];
            #pragma unroll
            for (int j = 0; j < 4; j++) {
                int col = n0 + n_w + 8 * j + 2 * tig;
                long long o0 = (long long)r0 * ldc + col;
                long long o1 = (long long)r1 * ldc + col;
                float2 a0 = *(const float2*)&Rb[o0];
                float2 a1 = *(const float2*)&Rb[o1];
                float2 v0 = make_float2(acc[i][j][0] + bm0 + a0.x,
                                        acc[i][j][1] + bm0 + a0.y);
                float2 v1 = make_float2(acc[i][j][2] + bm1 + a1.x,
                                        acc[i][j][3] + bm1 + a1.y);
                *(float2*)&C[o0] = v0;
                *(float2*)&C[o1] = v1;
            }
        }
    }
}

// ---------------------------------------------------------------------------
// Fused prologue: [0,4096) weight prep | [4096,4352) GN partial stats |
// [4352,4384) rowsum zero.
// ---------------------------------------------------------------------------
#define PREP_BLOCKS 4096
#define STAT_BLOCKS 256
#define ZERO_BLOCKS 32

__global__ __launch_bounds__(256) void prologue_kernel(
    const float* __restrict__ x,
    const float* __restrict__ wq, const float* __restrict__ wk,
    const float* __restrict__ wv, const float* __restrict__ wo,
    const float* __restrict__ bq, const float* __restrict__ bk,
    const float* __restrict__ bv,
    __nv_bfloat16* __restrict__ wqkv, __nv_bfloat16* __restrict__ wob,
    float* __restrict__ bqkv, float* __restrict__ ssum4,
    float* __restrict__ rowsum)
{
    const int blk = blockIdx.x;
    const int t = threadIdx.x;

    if (blk < PREP_BLOCKS) {
        const float qscale = 0.044194173824159216f * 1.4426950408889634f;
        int idx = blk * 256 + t;
        if (idx < NQKV * CCH) {
            int row = idx >> 9, col = idx & 511;
            int which = row >> 9, rr = row & 511;
            float v = which == 0 ? wq[rr * 512 + col] * qscale
                    : which == 1 ? wk[rr * 512 + col]
                                 : wv[rr * 512 + col];
            wqkv[idx] = __float2bfloat16_rn(v);
            if (idx < NQKV) {
                int w2 = idx >> 9, r2 = idx & 511;
                bqkv[idx] = w2 == 0 ? bq[r2] * qscale
                          : w2 == 1 ? bk[r2] : bv[r2];
            }
        } else {
            int j = idx - NQKV * CCH;
            wob[j] = __float2bfloat16_rn(wo[j]);
        }
    } else if (blk < PREP_BLOCKS + STAT_BLOCKS) {
        const int pb = blk - PREP_BLOCKS;
        const long long base = (long long)(pb >> 2) * 65536 + (pb & 3) * 16384;
        float s = 0.f, ss = 0.f;
        #pragma unroll 4
        for (int i = t; i < 16384; i += 256) {
            float v = x[base + i];
            s += v; ss += v * v;
        }
        #pragma unroll
        for (int off = 16; off; off >>= 1) {
            s  += __shfl_down_sync(0xffffffffu, s,  off);
            ss += __shfl_down_sync(0xffffffffu, ss, off);
        }
        __shared__ float shs[8], shss[8];
        int wid = t >> 5, lane = t & 31;
        if (lane == 0) { shs[wid] = s; shss[wid] = ss; }
        __syncthreads();
        if (t == 0) {
            float ts = 0.f, tss = 0.f;
            #pragma unroll
            for (int i = 0; i < 8; i++) { ts += shs[i]; tss += shss[i]; }
            ssum4[2 * pb]     = ts;
            ssum4[2 * pb + 1] = tss;
        }
    } else {
        int idx = (blk - PREP_BLOCKS - STAT_BLOCKS) * 256 + t;
        rowsum[idx] = 0.f;
    }
}

// ---------------------------------------------------------------------------
// GN apply + transpose (bf16 out); sums 4 stat partials inline
// ---------------------------------------------------------------------------
__global__ __launch_bounds__(256) void gn_apply_t_kernel(
    const float* __restrict__ x, const float* __restrict__ w,
    const float* __restrict__ b, const float* __restrict__ ssum4,
    __nv_bfloat16* __restrict__ ht)
{
    __shared__ float tile[32][33];
    const int p0 = blockIdx.x * 32;
    const int c0 = blockIdx.y * 32;
    const int bb = blockIdx.z;
    const int tx = threadIdx.x, ty = threadIdx.y;   // (32, 8)
    const long long xb = (long long)bb * CN;

    #pragma unroll
    for (int r = 0; r < 4; r++) {
        int cl = ty + 8 * r;
        tile[cl][tx] = x[xb + (long long)(c0 + cl) * NPIX + p0 + tx];
    }
    __syncthreads();
    const int c = c0 + tx;
    const int gidx = c >> 4;
    const int bg = bb * 32 + gidx;
    float ts = 0.f, tss = 0.f;
    #pragma unroll
    for (int pp = 0; pp < 4; pp++) {
        ts  += ssum4[2 * (bg * 4 + pp)];
        tss += ssum4[2 * (bg * 4 + pp) + 1];
    }
    const float mean = ts * (1.f / 65536.f);
    const float var  = tss * (1.f / 65536.f) - mean * mean;
    const float rstd = rsqrtf(var + GEPS);
    const float sc = rstd * w[c];
    const float sh = b[c] - mean * sc;
    #pragma unroll
    for (int r = 0; r < 4; r++) {
        int pl = ty + 8 * r;
        float v = tile[tx][pl] * sc + sh;
        ht[xb + (long long)(p0 + pl) * CCH + c] = __float2bfloat16_rn(v);
    }
}

// ---------------------------------------------------------------------------
extern "C" void kernel_launch(void* const* d_in, const int* in_sizes, int n_in,
                              void* d_out, int out_size)
{
    const float* x    = (const float*)d_in[0];
    const float* gn_w = (const float*)d_in[1];
    const float* gn_b = (const float*)d_in[2];
    const float* wq   = (const float*)d_in[3];
    const float* bq   = (const float*)d_in[4];
    const float* wk   = (const float*)d_in[5];
    const float* bk   = (const float*)d_in[6];
    const float* wv   = (const float*)d_in[7];
    const float* bv   = (const float*)d_in[8];
    const float* wo   = (const float*)d_in[9];
    const float* bo   = (const float*)d_in[10];
    float* out = (float*)d_out;

    __nv_bfloat16 *ht, *qkv, *p, *ot, *wqkv, *wob;
    float *bqkv, *ssum4, *rowsum;
    cudaGetSymbolAddress((void**)&ht,     g_ht);
    cudaGetSymbolAddress((void**)&qkv,    g_qkv);
    cudaGetSymbolAddress((void**)&p,      g_p);
    cudaGetSymbolAddress((void**)&ot,     g_ot);
    cudaGetSymbolAddress((void**)&wqkv,   g_wqkv);
    cudaGetSymbolAddress((void**)&wob,    g_wo);
    cudaGetSymbolAddress((void**)&bqkv,   g_bqkv);
    cudaGetSymbolAddress((void**)&ssum4,  g_ssum4);
    cudaGetSymbolAddress((void**)&rowsum, g_rowsum);

    cudaFuncSetAttribute(gemm_bf16_tc<1, false>,
        cudaFuncAttributeMaxDynamicSharedMemorySize, SMEM3_NT);
    cudaFuncSetAttribute(gemm_bf16_tc<2, false>,
        cudaFuncAttributeMaxDynamicSharedMemorySize, SMEM3_NT);
    cudaFuncSetAttribute(gemm_bf16_tc<3, true>,
        cudaFuncAttributeMaxDynamicSharedMemorySize, SMEM3_TR);
    cudaFuncSetAttribute(gemm_bf16_tc<4, false>,
        cudaFuncAttributeMaxDynamicSharedMemorySize, SMEM3_NT);

    // 0) fused prologue: weight prep + GN partial stats + rowsum zero
    prologue_kernel<<<PREP_BLOCKS + STAT_BLOCKS + ZERO_BLOCKS, 256>>>(
        x, wq, wk, wv, wo, bq, bk, bv, wqkv, wob, bqkv, ssum4, rowsum);

    // 1) GN apply + transpose -> hT bf16 [B][pix][C]
    gn_apply_t_kernel<<<dim3(NPIX / 32, CCH / 32, BATCH), dim3(32, 8)>>>(
        x, gn_w, gn_b, ssum4, ht);

    // 2) fused QKV: qkvT[pix][1536] = hT @ wqkv^T + bqkv[n]
    dim3 gQKV(NQKV / BN, NPIX / BM, BATCH);
    gemm_bf16_tc<1, false><<<gQKV, 256, SMEM3_NT>>>(
        ht, wqkv, qkv, bqkv, nullptr, CCH, CCH, CCH, NQKV,
        CN, 0, QKVN, 0, 0);

    // 3) P = exp2(qT @ kT^T) -> bf16, rowsum accumulated (log2e pre-folded)
    dim3 gS(NPIX / BN, NPIX / BM, BATCH);
    gemm_bf16_tc<2, false><<<gS, 256, SMEM3_NT>>>(
        qkv, qkv + 512, p, rowsum, nullptr, CCH, NQKV, NQKV, NPIX,
        QKVN, QKVN, NN, NPIX, 0);

    // 4) OT[pix][C] = (P @ vT) / rowsum[pix]
    dim3 gAV(CCH / BN, NPIX / BM, BATCH);
    gemm_bf16_tc<3, true><<<gAV, 256, SMEM3_TR>>>(
        p, qkv + 1024, ot, rowsum, nullptr, NPIX, NPIX, NQKV, CCH,
        NN, QKVN, CN, NPIX, 0);

    // 5) out = x + wo @ OT^T + bo[m]  (fp32)
    dim3 gF(NPIX / BN, CCH / BM, BATCH);
    gemm_bf16_tc<4, false><<<gF, 256, SMEM3_NT>>>(
        wob, ot, out, bo, x, CCH, CCH, CCH, NPIX,
        0, CN, CN, 0, CN);
}

// round 15
// speedup vs baseline: 1.2313x; 1.0207x over previous
#include <cuda_runtime.h>
#include <cuda_bf16.h>
#include <cstdint>

// B=2, C=512, N=4096. out = x + Wo@Attn(GN(x)) + bo, [B,C,H,W] fp32.
// Pipeline: prologue(weights->bf16, GN stats, zero) -> gn_apply(hT bf16)
//   -> qk GEMM -> [S-GEMM + V-GEMM fused in ONE launch] -> AV -> final.
#define BATCH 2
#define CCH   512
#define NPIX  4096
#define NQK   1024
#define GEPS  1e-6f

static const long long CN   = (long long)CCH * NPIX;    // 2M
static const long long NN   = (long long)NPIX * NPIX;   // 16M
static const long long QK2N = (long long)NPIX * NQK;    // 4M

// scratch (device globals)
__device__ __nv_bfloat16 g_ht [BATCH * NPIX * CCH];             // hT [B][pix][C]
__device__ __nv_bfloat16 g_qk [(long long)BATCH * NPIX * NQK];  // [B][pix][q|k]
__device__ __nv_bfloat16 g_v16[BATCH * CCH * NPIX];             // v [B][C][pix]
__device__ __nv_bfloat16 g_p  [(long long)BATCH * NPIX * NPIX]; // exp(S) bf16
__device__ __nv_bfloat16 g_ot [BATCH * NPIX * CCH];             // OT [B][pix][C]
__device__ __nv_bfloat16 g_wqk[NQK * CCH];                      // concat(wq*qs, wk)
__device__ __nv_bfloat16 g_wv16[CCH * CCH];
__device__ __nv_bfloat16 g_wo [CCH * CCH];
__device__ float         g_bqk[NQK];                            // concat(bq*qs, bk)
__device__ float         g_rowsum[BATCH * NPIX];
__device__ float         g_ssum4[BATCH * 32 * 4 * 2];           // GN partials

// ---------------------------------------------------------------------------
// PTX helpers
// ---------------------------------------------------------------------------
__device__ __forceinline__ void cpasync16(uint32_t s, const void* g) {
    asm volatile("cp.async.cg.shared.global [%0], [%1], 16;" :: "r"(s), "l"(g));
}
__device__ __forceinline__ uint32_t smem_u32(const void* p) {
    return (uint32_t)__cvta_generic_to_shared(p);
}
__device__ __forceinline__ void ldsm4(uint32_t r[4], uint32_t addr) {
    asm volatile("ldmatrix.sync.aligned.m8n8.x4.shared.b16 {%0,%1,%2,%3}, [%4];"
        : "=r"(r[0]), "=r"(r[1]), "=r"(r[2]), "=r"(r[3]) : "r"(addr));
}
__device__ __forceinline__ void mma_bf16(float c[4], const uint32_t a[4],
                                         const uint32_t b0, const uint32_t b1) {
    asm volatile(
        "mma.sync.aligned.m16n8k16.row.col.f32.bf16.bf16.f32 "
        "{%0,%1,%2,%3},{%4,%5,%6,%7},{%8,%9},{%0,%1,%2,%3};"
        : "+f"(c[0]), "+f"(c[1]), "+f"(c[2]), "+f"(c[3])
        : "r"(a[0]), "r"(a[1]), "r"(a[2]), "r"(a[3]), "r"(b0), "r"(b1));
}
__device__ __forceinline__ float ex2f(float x) {
    float y; asm("ex2.approx.ftz.f32 %0, %1;" : "=f"(y) : "f"(x));
    return y;
}

// ---------------------------------------------------------------------------
// Shared GEMM core (proven-best config): D[M][N] = A[M][K] * B[N][K]^T
// Block 128x128x64, 256 thr = 8 warps (2x4), warp tile 64x32, m16n8k16,
// 3-stage cp.async, conflict-free 144B-stride smem. All operands NT K-major.
// EPI: 1 = bf16 out + bias[n]                        (qk)
//      5 = bf16 out + bias[m]                        (v)
//      2 = exp2 + bf16 out + rowsum atomics          (S)
//      3 = bf16 out * (1/rs[m])                      (AV)
//      4 = fp32 out + bias[m] + residual             (final)
// ---------------------------------------------------------------------------
#define BM 128
#define BN 128
#define BK 64
#define ASTR 144
#define ASTAGE (BM * ASTR)
#define SMEM3 (6 * ASTAGE)   // 3 stages x (A+B) = 110592

template<int EPI>
__device__ __forceinline__ void gemm_core(
    const __nv_bfloat16* __restrict__ Ab, const __nv_bfloat16* __restrict__ Bb,
    void* __restrict__ Cz,
    const float* __restrict__ bias, float* __restrict__ rsz,
    const float* __restrict__ resz,
    int K, int lda, int ldb, int ldc, int m0, int n0)
{
    extern __shared__ char smem[];
    const uint32_t sbA = smem_u32(smem);
    const uint32_t sbB = sbA + 3 * ASTAGE;

    const int tid  = threadIdx.x;
    const int wid  = tid >> 5;
    const int lane = tid & 31;
    const int g    = lane >> 2;
    const int tig  = lane & 3;
    const int sub  = lane >> 3;
    const int r8   = lane & 7;
    const int m_w  = (wid >> 2) * 64;
    const int n_w  = (wid & 3) * 32;

    const __nv_bfloat16* Abt = Ab + (long long)m0 * lda;
    const __nv_bfloat16* Bbt = Bb + (long long)n0 * ldb;

    float acc[4][4][4];
    #pragma unroll
    for (int i = 0; i < 4; i++)
        #pragma unroll
        for (int j = 0; j < 4; j++)
            #pragma unroll
            for (int r = 0; r < 4; r++) acc[i][j][r] = 0.f;

    const int nk = K / BK;

    auto load = [&](int ks, int buf) {
        const uint32_t ab = sbA + buf * ASTAGE;
        const uint32_t bb = sbB + buf * ASTAGE;
        #pragma unroll
        for (int it = 0; it < 4; it++) {
            int s = tid + it * 256;
            int r = s >> 3, c = s & 7;
            cpasync16(ab + r * ASTR + c * 16,
                      Abt + (long long)r * lda + ks * BK + c * 8);
        }
        #pragma unroll
        for (int it = 0; it < 4; it++) {
            int s = tid + it * 256;
            int r = s >> 3, c = s & 7;
            cpasync16(bb + r * ASTR + c * 16,
                      Bbt + (long long)r * ldb + ks * BK + c * 8);
        }
        asm volatile("cp.async.commit_group;");
    };

    load(0, 0);
    if (nk > 1) load(1, 1);

    #pragma unroll 1
    for (int ks = 0; ks < nk; ks++) {
        const int buf = ks % 3;
        if (ks + 1 < nk) asm volatile("cp.async.wait_group 1;");
        else             asm volatile("cp.async.wait_group 0;");
        __syncthreads();
        if (ks + 2 < nk) load(ks + 2, (ks + 2) % 3);

        const uint32_t ab = sbA + buf * ASTAGE;
        const uint32_t bb = sbB + buf * ASTAGE;

        #pragma unroll
        for (int kk = 0; kk < 4; kk++) {
            uint32_t af[4][4];
            #pragma unroll
            for (int i = 0; i < 4; i++) {
                uint32_t addr = ab + (m_w + 16 * i + (sub & 1) * 8 + r8) * ASTR
                              + kk * 32 + (sub >> 1) * 16;
                ldsm4(af[i], addr);
            }
            uint32_t bf[4][2];
            #pragma unroll
            for (int jj = 0; jj < 2; jj++) {
                uint32_t t[4];
                uint32_t addr = bb + (n_w + 16 * jj + (sub >> 1) * 8 + r8) * ASTR
                              + kk * 32 + (sub & 1) * 16;
                ldsm4(t, addr);
                bf[2 * jj][0] = t[0]; bf[2 * jj][1] = t[1];
                bf[2 * jj + 1][0] = t[2]; bf[2 * jj + 1][1] = t[3];
            }
            #pragma unroll
            for (int i = 0; i < 4; i++)
                #pragma unroll
                for (int j = 0; j < 4; j++)
                    mma_bf16(acc[i][j], af[i], bf[j][0], bf[j][1]);
        }
    }

    // ------------------------------ epilogues ------------------------------
    if (EPI == 1) {           // bf16 out + bias[n]
        __nv_bfloat16* C = (__nv_bfloat16*)Cz;
        #pragma unroll
        for (int i = 0; i < 4; i++) {
            int r0 = m0 + m_w + 16 * i + g, r1 = r0 + 8;
            #pragma unroll
            for (int j = 0; j < 4; j++) {
                int col = n0 + n_w + 8 * j + 2 * tig;
                float bn0 = bias[col], bn1 = bias[col + 1];
                *(__nv_bfloat162*)&C[(long long)r0 * ldc + col] =
                    __float22bfloat162_rn(make_float2(acc[i][j][0] + bn0,
                                                      acc[i][j][1] + bn1));
                *(__nv_bfloat162*)&C[(long long)r1 * ldc + col] =
                    __float22bfloat162_rn(make_float2(acc[i][j][2] + bn0,
                                                      acc[i][j][3] + bn1));
            }
        }
    } else if (EPI == 5) {    // bf16 out + bias[m]
        __nv_bfloat16* C = (__nv_bfloat16*)Cz;
        #pragma unroll
        for (int i = 0; i < 4; i++) {
            int r0 = m0 + m_w + 16 * i + g, r1 = r0 + 8;
            float bm0 = bias[r0], bm1 = bias[r1];
            #pragma unroll
            for (int j = 0; j < 4; j++) {
                int col = n0 + n_w + 8 * j + 2 * tig;
                *(__nv_bfloat162*)&C[(long long)r0 * ldc + col] =
                    __float22bfloat162_rn(make_float2(acc[i][j][0] + bm0,
                                                      acc[i][j][1] + bm0));
                *(__nv_bfloat162*)&C[(long long)r1 * ldc + col] =
                    __float22bfloat162_rn(make_float2(acc[i][j][2] + bm1,
                                                      acc[i][j][3] + bm1));
            }
        }
    } else if (EPI == 2) {    // exp2, bf16 out, rowsum atomics
        __nv_bfloat16* C = (__nv_bfloat16*)Cz;
        #pragma unroll
        for (int i = 0; i < 4; i++) {
            int r0 = m0 + m_w + 16 * i + g, r1 = r0 + 8;
            float s0 = 0.f, s1 = 0.f;
            #pragma unroll
            for (int j = 0; j < 4; j++) {
                int col = n0 + n_w + 8 * j + 2 * tig;
                float e0 = ex2f(acc[i][j][0]);
                float e1 = ex2f(acc[i][j][1]);
                float e2 = ex2f(acc[i][j][2]);
                float e3 = ex2f(acc[i][j][3]);
                s0 += e0 + e1; s1 += e2 + e3;
                *(__nv_bfloat162*)&C[(long long)r0 * ldc + col] =
                    __float22bfloat162_rn(make_float2(e0, e1));
                *(__nv_bfloat162*)&C[(long long)r1 * ldc + col] =
                    __float22bfloat162_rn(make_float2(e2, e3));
            }
            s0 += __shfl_xor_sync(0xffffffffu, s0, 1);
            s0 += __shfl_xor_sync(0xffffffffu, s0, 2);
            s1 += __shfl_xor_sync(0xffffffffu, s1, 1);
            s1 += __shfl_xor_sync(0xffffffffu, s1, 2);
            if (tig == 0) {
                atomicAdd(&rsz[r0], s0);
                atomicAdd(&rsz[r1], s1);
            }
        }
    } else if (EPI == 3) {    // bf16 out scaled by 1/rs[m]
        __nv_bfloat16* C = (__nv_bfloat16*)Cz;
        #pragma unroll
        for (int i = 0; i < 4; i++) {
            int r0 = m0 + m_w + 16 * i + g, r1 = r0 + 8;
            float i0 = 1.f / rsz[r0];
            float i1 = 1.f / rsz[r1];
            #pragma unroll
            for (int j = 0; j < 4; j++) {
                int col = n0 + n_w + 8 * j + 2 * tig;
                *(__nv_bfloat162*)&C[(long long)r0 * ldc + col] =
                    __float22bfloat162_rn(make_float2(acc[i][j][0] * i0,
                                                      acc[i][j][1] * i0));
                *(__nv_bfloat162*)&C[(long long)r1 * ldc + col] =
                    __float22bfloat162_rn(make_float2(acc[i][j][2] * i1,
                                                      acc[i][j][3] * i1));
            }
        }
    } else {                  // EPI == 4: fp32 out + bias[m] + residual
        float* C = (float*)Cz;
        #pragma unroll
        for (int i = 0; i < 4; i++) {
            int r0 = m0 + m_w + 16 * i + g, r1 = r0 + 8;
            float bm0 = bias[r0], bm1 = bias[r1];
            #pragma unroll
            for (int j = 0; j < 4; j++) {
                int col = n0 + n_w + 8 * j + 2 * tig;
                long long o0 = (long long)r0 * ldc + col;
                long long o1 = (long long)r1 * ldc + col;
                float2 a0 = *(const float2*)&resz[o0];
                float2 a1 = *(const float2*)&resz[o1];
                float2 v0 = make_float2(acc[i][j][0] + bm0 + a0.x,
                                        acc[i][j][1] + bm0 + a0.y);
                float2 v1 = make_float2(acc[i][j][2] + bm1 + a1.x,
                                        acc[i][j][3] + bm1 + a1.y);
                *(float2*)&C[o0] = v0;
                *(float2*)&C[o1] = v1;
            }
        }
    }
}

// Plain GEMM launcher (qk / AV / final)
template<int EPI>
__global__ __launch_bounds__(256, 2) void gemm_tc(
    const __nv_bfloat16* __restrict__ A, const __nv_bfloat16* __restrict__ B,
    void* __restrict__ Cv,
    const float* __restrict__ bias, float* __restrict__ aux,
    const float* __restrict__ res,
    int K, int lda, int ldb, int ldc,
    long long sA, long long sB, long long sC, long long sAux, long long sR)
{
    const int z = blockIdx.z;
    gemm_core<EPI>(
        A + (long long)z * sA, B + (long long)z * sB,
        (char*)Cv + (long long)z * sC * (EPI == 4 ? 4 : 2),
        bias, aux ? aux + (long long)z * sAux : nullptr,
        res ? res + (long long)z * sR : nullptr,
        K, lda, ldb, ldc, blockIdx.y * BM, blockIdx.x * BN);
}

// Fused S + V launch: blocks [0,2048) = S tiles, [2048,2304) = V tiles.
__global__ __launch_bounds__(256, 2) void sv_kernel(
    const __nv_bfloat16* __restrict__ qk, __nv_bfloat16* __restrict__ p,
    float* __restrict__ rowsum,
    const __nv_bfloat16* __restrict__ wv16, const __nv_bfloat16* __restrict__ ht,
    __nv_bfloat16* __restrict__ v16, const float* __restrict__ bv)
{
    const int idx = blockIdx.x;
    if (idx < 2048) {
        // S: P = exp2(q @ k^T), M=N=4096, K=512
        const int b = idx >> 10, r = idx & 1023;
        const int m0 = ((r >> 5) & 31) * BM, n0 = (r & 31) * BN;
        const __nv_bfloat16* qkz = qk + (long long)b * QK2N;
        gemm_core<2>(qkz, qkz + 512, p + (long long)b * NN,
                     nullptr, rowsum + (long long)b * NPIX, nullptr,
                     CCH, NQK, NQK, NPIX, m0, n0);
    } else {
        // V: v16[C][pix] = wv @ ht^T + bv[m], M=512, N=4096, K=512
        const int t = idx - 2048;
        const int b = t >> 7, r = t & 127;
        const int m0 = ((r >> 5) & 3) * BM, n0 = (r & 31) * BN;
        gemm_core<5>(wv16, ht + (long long)b * CN, v16 + (long long)b * CN,
                     bv, nullptr, nullptr,
                     CCH, CCH, CCH, NPIX, m0, n0);
    }
}

// ---------------------------------------------------------------------------
// Fused prologue: [0,2048) wqk prep | [2048,3072) wv16 | [3072,4096) wo16 |
// [4096,4352) GN partial stats | [4352,4384) rowsum zero.
// ---------------------------------------------------------------------------
#define PQ_B 2048
#define PV_B 1024
#define PO_B 1024
#define PS_B 256
#define PZ_B 32
#define PRO_BLOCKS (PQ_B + PV_B + PO_B + PS_B + PZ_B)

__global__ __launch_bounds__(256) void prologue_kernel(
    const float* __restrict__ x,
    const float* __restrict__ wq, const float* __restrict__ wk,
    const float* __restrict__ wv, const float* __restrict__ wo,
    const float* __restrict__ bq, const float* __restrict__ bk,
    __nv_bfloat16* __restrict__ wqk, __nv_bfloat16* __restrict__ wv16,
    __nv_bfloat16* __restrict__ wo16,
    float* __restrict__ bqk, float* __restrict__ ssum4,
    float* __restrict__ rowsum)
{
    const int blk = blockIdx.x;
    const int t = threadIdx.x;

    if (blk < PQ_B) {
        const float qscale = 0.044194173824159216f * 1.4426950408889634f;
        int idx = blk * 256 + t;
        int row = idx >> 9, col = idx & 511;
        int which = row >> 9, rr = row & 511;
        float v = which == 0 ? wq[rr * 512 + col] * qscale : wk[rr * 512 + col];
        wqk[idx] = __float2bfloat16_rn(v);
        if (idx < NQK) {
            int w2 = idx >> 9, r2 = idx & 511;
            bqk[idx] = w2 == 0 ? bq[r2] * qscale : bk[r2];
        }
    } else if (blk < PQ_B + PV_B) {
        int idx = (blk - PQ_B) * 256 + t;
        wv16[idx] = __float2bfloat16_rn(wv[idx]);
    } else if (blk < PQ_B + PV_B + PO_B) {
        int idx = (blk - PQ_B - PV_B) * 256 + t;
        wo16[idx] = __float2bfloat16_rn(wo[idx]);
    } else if (blk < PQ_B + PV_B + PO_B + PS_B) {
        const int pb = blk - PQ_B - PV_B - PO_B;
        const long long base = (long long)(pb >> 2) * 65536 + (pb & 3) * 16384;
        float s = 0.f, ss = 0.f;
        #pragma unroll 4
        for (int i = t; i < 16384; i += 256) {
            float v = x[base + i];
            s += v; ss += v * v;
        }
        #pragma unroll
        for (int off = 16; off; off >>= 1) {
            s  += __shfl_down_sync(0xffffffffu, s,  off);
            ss += __shfl_down_sync(0xffffffffu, ss, off);
        }
        __shared__ float shs[8], shss[8];
        int wid = t >> 5, lane = t & 31;
        if (lane == 0) { shs[wid] = s; shss[wid] = ss; }
        __syncthreads();
        if (t == 0) {
            float ts = 0.f, tss = 0.f;
            #pragma unroll
            for (int i = 0; i < 8; i++) { ts += shs[i]; tss += shss[i]; }
            ssum4[2 * pb]     = ts;
            ssum4[2 * pb + 1] = tss;
        }
    } else {
        int idx = (blk - PQ_B - PV_B - PO_B - PS_B) * 256 + t;
        rowsum[idx] = 0.f;
    }
}

// ---------------------------------------------------------------------------
// GN apply + transpose (bf16 out); sums 4 stat partials inline
// ---------------------------------------------------------------------------
__global__ __launch_bounds__(256) void gn_apply_t_kernel(
    const float* __restrict__ x, const float* __restrict__ w,
    const float* __restrict__ b, const float* __restrict__ ssum4,
    __nv_bfloat16* __restrict__ ht)
{
    __shared__ float tile[32][33];
    const int p0 = blockIdx.x * 32;
    const int c0 = blockIdx.y * 32;
    const int bb = blockIdx.z;
    const int tx = threadIdx.x, ty = threadIdx.y;   // (32, 8)
    const long long xb = (long long)bb * CN;

    #pragma unroll
    for (int r = 0; r < 4; r++) {
        int cl = ty + 8 * r;
        tile[cl][tx] = x[xb + (long long)(c0 + cl) * NPIX + p0 + tx];
    }
    __syncthreads();
    const int c = c0 + tx;
    const int gidx = c >> 4;
    const int bg = bb * 32 + gidx;
    float ts = 0.f, tss = 0.f;
    #pragma unroll
    for (int pp = 0; pp < 4; pp++) {
        ts  += ssum4[2 * (bg * 4 + pp)];
        tss += ssum4[2 * (bg * 4 + pp) + 1];
    }
    const float mean = ts * (1.f / 65536.f);
    const float var  = tss * (1.f / 65536.f) - mean * mean;
    const float rstd = rsqrtf(var + GEPS);
    const float sc = rstd * w[c];
    const float sh = b[c] - mean * sc;
    #pragma unroll
    for (int r = 0; r < 4; r++) {
        int pl = ty + 8 * r;
        float v = tile[tx][pl] * sc + sh;
        ht[xb + (long long)(p0 + pl) * CCH + c] = __float2bfloat16_rn(v);
    }
}

// ---------------------------------------------------------------------------
extern "C" void kernel_launch(void* const* d_in, const int* in_sizes, int n_in,
                              void* d_out, int out_size)
{
    const float* x    = (const float*)d_in[0];
    const float* gn_w = (const float*)d_in[1];
    const float* gn_b = (const float*)d_in[2];
    const float* wq   = (const float*)d_in[3];
    const float* bq   = (const float*)d_in[4];
    const float* wk   = (const float*)d_in[5];
    const float* bk   = (const float*)d_in[6];
    const float* wv   = (const float*)d_in[7];
    const float* bv   = (const float*)d_in[8];
    const float* wo   = (const float*)d_in[9];
    const float* bo   = (const float*)d_in[10];
    float* out = (float*)d_out;

    __nv_bfloat16 *ht, *qk, *v16, *p, *ot, *wqk, *wv16, *wo16;
    float *bqk, *rowsum, *ssum4;
    cudaGetSymbolAddress((void**)&ht,     g_ht);
    cudaGetSymbolAddress((void**)&qk,     g_qk);
    cudaGetSymbolAddress((void**)&v16,    g_v16);
    cudaGetSymbolAddress((void**)&p,      g_p);
    cudaGetSymbolAddress((void**)&ot,     g_ot);
    cudaGetSymbolAddress((void**)&wqk,    g_wqk);
    cudaGetSymbolAddress((void**)&wv16,   g_wv16);
    cudaGetSymbolAddress((void**)&wo16,   g_wo);
    cudaGetSymbolAddress((void**)&bqk,    g_bqk);
    cudaGetSymbolAddress((void**)&rowsum, g_rowsum);
    cudaGetSymbolAddress((void**)&ssum4,  g_ssum4);

    cudaFuncSetAttribute(gemm_tc<1>,
        cudaFuncAttributeMaxDynamicSharedMemorySize, SMEM3);
    cudaFuncSetAttribute(gemm_tc<3>,
        cudaFuncAttributeMaxDynamicSharedMemorySize, SMEM3);
    cudaFuncSetAttribute(gemm_tc<4>,
        cudaFuncAttributeMaxDynamicSharedMemorySize, SMEM3);
    cudaFuncSetAttribute(sv_kernel,
        cudaFuncAttributeMaxDynamicSharedMemorySize, SMEM3);

    // 0) fused prologue
    prologue_kernel<<<PRO_BLOCKS, 256>>>(
        x, wq, wk, wv, wo, bq, bk, wqk, wv16, wo16, bqk, ssum4, rowsum);

    // 1) GN apply + transpose -> hT bf16 [B][pix][C]
    gn_apply_t_kernel<<<dim3(NPIX / 32, CCH / 32, BATCH), dim3(32, 8)>>>(
        x, gn_w, gn_b, ssum4, ht);

    // 2) qk[pix][1024] = ht @ wqk^T + bqk[n]
    dim3 gQK(NQK / BN, NPIX / BM, BATCH);        // (8, 32, 2) = 512 CTAs
    gemm_tc<1><<<gQK, 256, SMEM3>>>(
        ht, wqk, qk, bqk, nullptr, nullptr,
        CCH, CCH, CCH, NQK, CN, 0, QK2N, 0, 0);

    // 3) fused S + V: 2048 S tiles + 256 V tiles in one launch
    sv_kernel<<<2048 + 256, 256, SMEM3>>>(qk, p, rowsum, wv16, ht, v16, bv);

    // 4) OT[pix][C] = (P @ v16^T) / rowsum[pix]   (NT: v16 is [C][pix])
    dim3 gAV(CCH / BN, NPIX / BM, BATCH);        // (4, 32, 2) = 256 CTAs
    gemm_tc<3><<<gAV, 256, SMEM3>>>(
        p, v16, ot, nullptr, rowsum, nullptr,
        NPIX, NPIX, NPIX, CCH, NN, CN, CN, NPIX, 0);

    // 5) out = x + wo @ OT^T + bo[m]  (fp32)
    dim3 gF(NPIX / BN, CCH / BM, BATCH);         // (32, 4, 2) = 256 CTAs
    gemm_tc<4><<<gF, 256, SMEM3>>>(
        wo16, ot, out, bo, nullptr, x,
        CCH, CCH, CCH, NPIX, 0, CN, CN, 0, CN);
}

// round 16
// speedup vs baseline: 1.2332x; 1.0016x over previous
#include <cuda_runtime.h>
#include <cuda_bf16.h>
#include <cstdint>

// B=2, C=512, N=4096. out = x + Wo@Attn(GN(x)) + bo, [B,C,H,W] fp32.
// Pipeline: prologue(wqk prep, GN stats, zero) -> gn_apply(hT bf16)
//   -> [qk GEMM + wv/wo bf16 conversion packed] -> [S + V fused] -> AV -> final.
#define BATCH 2
#define CCH   512
#define NPIX  4096
#define NQK   1024
#define GEPS  1e-6f

static const long long CN   = (long long)CCH * NPIX;    // 2M
static const long long NN   = (long long)NPIX * NPIX;   // 16M
static const long long QK2N = (long long)NPIX * NQK;    // 4M

// scratch (device globals)
__device__ __nv_bfloat16 g_ht [BATCH * NPIX * CCH];             // hT [B][pix][C]
__device__ __nv_bfloat16 g_qk [(long long)BATCH * NPIX * NQK];  // [B][pix][q|k]
__device__ __nv_bfloat16 g_v16[BATCH * CCH * NPIX];             // v [B][C][pix]
__device__ __nv_bfloat16 g_p  [(long long)BATCH * NPIX * NPIX]; // exp(S) bf16
__device__ __nv_bfloat16 g_ot [BATCH * NPIX * CCH];             // OT [B][pix][C]
__device__ __nv_bfloat16 g_wqk[NQK * CCH];                      // concat(wq*qs, wk)
__device__ __nv_bfloat16 g_wv16[CCH * CCH];
__device__ __nv_bfloat16 g_wo [CCH * CCH];
__device__ float         g_bqk[NQK];                            // concat(bq*qs, bk)
__device__ float         g_rowsum[BATCH * NPIX];
__device__ float         g_ssum4[BATCH * 32 * 4 * 2];           // GN partials

// ---------------------------------------------------------------------------
// PTX helpers
// ---------------------------------------------------------------------------
__device__ __forceinline__ void cpasync16(uint32_t s, const void* g) {
    asm volatile("cp.async.cg.shared.global [%0], [%1], 16;" :: "r"(s), "l"(g));
}
__device__ __forceinline__ uint32_t smem_u32(const void* p) {
    return (uint32_t)__cvta_generic_to_shared(p);
}
__device__ __forceinline__ void ldsm4(uint32_t r[4], uint32_t addr) {
    asm volatile("ldmatrix.sync.aligned.m8n8.x4.shared.b16 {%0,%1,%2,%3}, [%4];"
        : "=r"(r[0]), "=r"(r[1]), "=r"(r[2]), "=r"(r[3]) : "r"(addr));
}
__device__ __forceinline__ void mma_bf16(float c[4], const uint32_t a[4],
                                         const uint32_t b0, const uint32_t b1) {
    asm volatile(
        "mma.sync.aligned.m16n8k16.row.col.f32.bf16.bf16.f32 "
        "{%0,%1,%2,%3},{%4,%5,%6,%7},{%8,%9},{%0,%1,%2,%3};"
        : "+f"(c[0]), "+f"(c[1]), "+f"(c[2]), "+f"(c[3])
        : "r"(a[0]), "r"(a[1]), "r"(a[2]), "r"(a[3]), "r"(b0), "r"(b1));
}
__device__ __forceinline__ float ex2f(float x) {
    float y; asm("ex2.approx.ftz.f32 %0, %1;" : "=f"(y) : "f"(x));
    return y;
}

// ---------------------------------------------------------------------------
// Shared GEMM core (proven-best config): D[M][N] = A[M][K] * B[N][K]^T
// Block 128x128x64, 256 thr = 8 warps (2x4), warp tile 64x32, m16n8k16,
// 3-stage cp.async, conflict-free 144B-stride smem. All operands NT K-major.
// EPI: 1 = bf16 out + bias[n]   (qk)
//      5 = bf16 out + bias[m]   (v)
//      2 = exp2 + bf16 out + rowsum atomics   (S)
//      3 = bf16 out * (1/rs[m])               (AV)
//      4 = fp32 out + bias[m] + residual      (final)
// ---------------------------------------------------------------------------
#define BM 128
#define BN 128
#define BK 64
#define ASTR 144
#define ASTAGE (BM * ASTR)
#define SMEM3 (6 * ASTAGE)   // 110592

template<int EPI>
__device__ __forceinline__ void gemm_core(
    const __nv_bfloat16* __restrict__ Ab, const __nv_bfloat16* __restrict__ Bb,
    void* __restrict__ Cz,
    const float* __restrict__ bias, float* __restrict__ rsz,
    const float* __restrict__ resz,
    int K, int lda, int ldb, int ldc, int m0, int n0)
{
    extern __shared__ char smem[];
    const uint32_t sbA = smem_u32(smem);
    const uint32_t sbB = sbA + 3 * ASTAGE;

    const int tid  = threadIdx.x;
    const int wid  = tid >> 5;
    const int lane = tid & 31;
    const int g    = lane >> 2;
    const int tig  = lane & 3;
    const int sub  = lane >> 3;
    const int r8   = lane & 7;
    const int m_w  = (wid >> 2) * 64;
    const int n_w  = (wid & 3) * 32;

    const __nv_bfloat16* Abt = Ab + (long long)m0 * lda;
    const __nv_bfloat16* Bbt = Bb + (long long)n0 * ldb;

    float acc[4][4][4];
    #pragma unroll
    for (int i = 0; i < 4; i++)
        #pragma unroll
        for (int j = 0; j < 4; j++)
            #pragma unroll
            for (int r = 0; r < 4; r++) acc[i][j][r] = 0.f;

    const int nk = K / BK;

    auto load = [&](int ks, int buf) {
        const uint32_t ab = sbA + buf * ASTAGE;
        const uint32_t bb = sbB + buf * ASTAGE;
        #pragma unroll
        for (int it = 0; it < 4; it++) {
            int s = tid + it * 256;
            int r = s >> 3, c = s & 7;
            cpasync16(ab + r * ASTR + c * 16,
                      Abt + (long long)r * lda + ks * BK + c * 8);
        }
        #pragma unroll
        for (int it = 0; it < 4; it++) {
            int s = tid + it * 256;
            int r = s >> 3, c = s & 7;
            cpasync16(bb + r * ASTR + c * 16,
                      Bbt + (long long)r * ldb + ks * BK + c * 8);
        }
        asm volatile("cp.async.commit_group;");
    };

    load(0, 0);
    if (nk > 1) load(1, 1);

    #pragma unroll 1
    for (int ks = 0; ks < nk; ks++) {
        const int buf = ks % 3;
        if (ks + 1 < nk) asm volatile("cp.async.wait_group 1;");
        else             asm volatile("cp.async.wait_group 0;");
        __syncthreads();
        if (ks + 2 < nk) load(ks + 2, (ks + 2) % 3);

        const uint32_t ab = sbA + buf * ASTAGE;
        const uint32_t bb = sbB + buf * ASTAGE;

        #pragma unroll
        for (int kk = 0; kk < 4; kk++) {
            uint32_t af[4][4];
            #pragma unroll
            for (int i = 0; i < 4; i++) {
                uint32_t addr = ab + (m_w + 16 * i + (sub & 1) * 8 + r8) * ASTR
                              + kk * 32 + (sub >> 1) * 16;
                ldsm4(af[i], addr);
            }
            uint32_t bf[4][2];
            #pragma unroll
            for (int jj = 0; jj < 2; jj++) {
                uint32_t t[4];
                uint32_t addr = bb + (n_w + 16 * jj + (sub >> 1) * 8 + r8) * ASTR
                              + kk * 32 + (sub & 1) * 16;
                ldsm4(t, addr);
                bf[2 * jj][0] = t[0]; bf[2 * jj][1] = t[1];
                bf[2 * jj + 1][0] = t[2]; bf[2 * jj + 1][1] = t[3];
            }
            #pragma unroll
            for (int i = 0; i < 4; i++)
                #pragma unroll
                for (int j = 0; j < 4; j++)
                    mma_bf16(acc[i][j], af[i], bf[j][0], bf[j][1]);
        }
    }

    // ------------------------------ epilogues ------------------------------
    if (EPI == 1) {
        __nv_bfloat16* C = (__nv_bfloat16*)Cz;
        #pragma unroll
        for (int i = 0; i < 4; i++) {
            int r0 = m0 + m_w + 16 * i + g, r1 = r0 + 8;
            #pragma unroll
            for (int j = 0; j < 4; j++) {
                int col = n0 + n_w + 8 * j + 2 * tig;
                float bn0 = bias[col], bn1 = bias[col + 1];
                *(__nv_bfloat162*)&C[(long long)r0 * ldc + col] =
                    __float22bfloat162_rn(make_float2(acc[i][j][0] + bn0,
                                                      acc[i][j][1] + bn1));
                *(__nv_bfloat162*)&C[(long long)r1 * ldc + col] =
                    __float22bfloat162_rn(make_float2(acc[i][j][2] + bn0,
                                                      acc[i][j][3] + bn1));
            }
        }
    } else if (EPI == 5) {
        __nv_bfloat16* C = (__nv_bfloat16*)Cz;
        #pragma unroll
        for (int i = 0; i < 4; i++) {
            int r0 = m0 + m_w + 16 * i + g, r1 = r0 + 8;
            float bm0 = bias[r0], bm1 = bias[r1];
            #pragma unroll
            for (int j = 0; j < 4; j++) {
                int col = n0 + n_w + 8 * j + 2 * tig;
                *(__nv_bfloat162*)&C[(long long)r0 * ldc + col] =
                    __float22bfloat162_rn(make_float2(acc[i][j][0] + bm0,
                                                      acc[i][j][1] + bm0));
                *(__nv_bfloat162*)&C[(long long)r1 * ldc + col] =
                    __float22bfloat162_rn(make_float2(acc[i][j][2] + bm1,
                                                      acc[i][j][3] + bm1));
            }
        }
    } else if (EPI == 2) {
        __nv_bfloat16* C = (__nv_bfloat16*)Cz;
        #pragma unroll
        for (int i = 0; i < 4; i++) {
            int r0 = m0 + m_w + 16 * i + g, r1 = r0 + 8;
            float s0 = 0.f, s1 = 0.f;
            #pragma unroll
            for (int j = 0; j < 4; j++) {
                int col = n0 + n_w + 8 * j + 2 * tig;
                float e0 = ex2f(acc[i][j][0]);
                float e1 = ex2f(acc[i][j][1]);
                float e2 = ex2f(acc[i][j][2]);
                float e3 = ex2f(acc[i][j][3]);
                s0 += e0 + e1; s1 += e2 + e3;
                *(__nv_bfloat162*)&C[(long long)r0 * ldc + col] =
                    __float22bfloat162_rn(make_float2(e0, e1));
                *(__nv_bfloat162*)&C[(long long)r1 * ldc + col] =
                    __float22bfloat162_rn(make_float2(e2, e3));
            }
            s0 += __shfl_xor_sync(0xffffffffu, s0, 1);
            s0 += __shfl_xor_sync(0xffffffffu, s0, 2);
            s1 += __shfl_xor_sync(0xffffffffu, s1, 1);
            s1 += __shfl_xor_sync(0xffffffffu, s1, 2);
            if (tig == 0) {
                atomicAdd(&rsz[r0], s0);
                atomicAdd(&rsz[r1], s1);
            }
        }
    } else if (EPI == 3) {
        __nv_bfloat16* C = (__nv_bfloat16*)Cz;
        #pragma unroll
        for (int i = 0; i < 4; i++) {
            int r0 = m0 + m_w + 16 * i + g, r1 = r0 + 8;
            float i0 = 1.f / rsz[r0];
            float i1 = 1.f / rsz[r1];
            #pragma unroll
            for (int j = 0; j < 4; j++) {
                int col = n0 + n_w + 8 * j + 2 * tig;
                *(__nv_bfloat162*)&C[(long long)r0 * ldc + col] =
                    __float22bfloat162_rn(make_float2(acc[i][j][0] * i0,
                                                      acc[i][j][1] * i0));
                *(__nv_bfloat162*)&C[(long long)r1 * ldc + col] =
                    __float22bfloat162_rn(make_float2(acc[i][j][2] * i1,
                                                      acc[i][j][3] * i1));
            }
        }
    } else {
        float* C = (float*)Cz;
        #pragma unroll
        for (int i = 0; i < 4; i++) {
            int r0 = m0 + m_w + 16 * i + g, r1 = r0 + 8;
            float bm0 = bias[r0], bm1 = bias[r1];
            #pragma unroll
            for (int j = 0; j < 4; j++) {
                int col = n0 + n_w + 8 * j + 2 * tig;
                long long o0 = (long long)r0 * ldc + col;
                long long o1 = (long long)r1 * ldc + col;
                float2 a0 = *(const float2*)&resz[o0];
                float2 a1 = *(const float2*)&resz[o1];
                float2 v0 = make_float2(acc[i][j][0] + bm0 + a0.x,
                                        acc[i][j][1] + bm0 + a0.y);
                float2 v1 = make_float2(acc[i][j][2] + bm1 + a1.x,
                                        acc[i][j][3] + bm1 + a1.y);
                *(float2*)&C[o0] = v0;
                *(float2*)&C[o1] = v1;
            }
        }
    }
}

// Plain GEMM launcher (AV / final)
template<int EPI>
__global__ __launch_bounds__(256, 2) void gemm_tc(
    const __nv_bfloat16* __restrict__ A, const __nv_bfloat16* __restrict__ B,
    void* __restrict__ Cv,
    const float* __restrict__ bias, float* __restrict__ aux,
    const float* __restrict__ res,
    int K, int lda, int ldb, int ldc,
    long long sA, long long sB, long long sC, long long sAux, long long sR)
{
    const int z = blockIdx.z;
    gemm_core<EPI>(
        A + (long long)z * sA, B + (long long)z * sB,
        (char*)Cv + (long long)z * sC * (EPI == 4 ? 4 : 2),
        bias, aux ? aux + (long long)z * sAux : nullptr,
        res ? res + (long long)z * sR : nullptr,
        K, lda, ldb, ldc, blockIdx.y * BM, blockIdx.x * BN);
}

// qk GEMM (512 CTAs) + wv/wo bf16 conversion (2048 micro-blocks) in one launch.
// Conversion blocks fill qk's ragged second wave.
__global__ __launch_bounds__(256, 2) void qk_conv_kernel(
    const __nv_bfloat16* __restrict__ ht, const __nv_bfloat16* __restrict__ wqk,
    __nv_bfloat16* __restrict__ qk, const float* __restrict__ bqk,
    const float* __restrict__ wv, const float* __restrict__ wo,
    __nv_bfloat16* __restrict__ wv16, __nv_bfloat16* __restrict__ wo16)
{
    const int idx = blockIdx.x;
    if (idx < 512) {
        // qk: [pix][1024] = ht @ wqk^T + bqk[n];  M=4096, N=1024, K=512
        const int b = idx >> 8, r = idx & 255;
        const int m0 = (r >> 3) * BM, n0 = (r & 7) * BN;
        gemm_core<1>(ht + (long long)b * CN, wqk,
                     qk + (long long)b * QK2N,
                     bqk, nullptr, nullptr,
                     CCH, CCH, CCH, NQK, m0, n0);
    } else {
        // fp32 -> bf16 weight conversion, 1024 elems per block
        const int t = idx - 512;                    // 0..2047
        const int base = (t & 1023) * 256 + (int)threadIdx.x;  // elem/4 index
        const float* src = (t < 1024) ? wv : wo;
        __nv_bfloat16* dst = (t < 1024) ? wv16 : wo16;
        float4 v = *(const float4*)&src[base * 4];
        __nv_bfloat162 lo = __float22bfloat162_rn(make_float2(v.x, v.y));
        __nv_bfloat162 hi = __float22bfloat162_rn(make_float2(v.z, v.w));
        *(__nv_bfloat162*)&dst[base * 4]     = lo;
        *(__nv_bfloat162*)&dst[base * 4 + 2] = hi;
    }
}

// Fused S + V launch: blocks [0,2048) = S tiles, [2048,2304) = V tiles.
__global__ __launch_bounds__(256, 2) void sv_kernel(
    const __nv_bfloat16* __restrict__ qk, __nv_bfloat16* __restrict__ p,
    float* __restrict__ rowsum,
    const __nv_bfloat16* __restrict__ wv16, const __nv_bfloat16* __restrict__ ht,
    __nv_bfloat16* __restrict__ v16, const float* __restrict__ bv)
{
    const int idx = blockIdx.x;
    if (idx < 2048) {
        const int b = idx >> 10, r = idx & 1023;
        const int m0 = ((r >> 5) & 31) * BM, n0 = (r & 31) * BN;
        const __nv_bfloat16* qkz = qk + (long long)b * QK2N;
        gemm_core<2>(qkz, qkz + 512, p + (long long)b * NN,
                     nullptr, rowsum + (long long)b * NPIX, nullptr,
                     CCH, NQK, NQK, NPIX, m0, n0);
    } else {
        const int t = idx - 2048;
        const int b = t >> 7, r = t & 127;
        const int m0 = ((r >> 5) & 3) * BM, n0 = (r & 31) * BN;
        gemm_core<5>(wv16, ht + (long long)b * CN, v16 + (long long)b * CN,
                     bv, nullptr, nullptr,
                     CCH, CCH, CCH, NPIX, m0, n0);
    }
}

// ---------------------------------------------------------------------------
// Prologue: [0,2048) wqk prep | [2048,2304) GN partial stats | [2304,2336) zero
// ---------------------------------------------------------------------------
#define PQ_B 2048
#define PS_B 256
#define PZ_B 32
#define PRO_BLOCKS (PQ_B + PS_B + PZ_B)

__global__ __launch_bounds__(256) void prologue_kernel(
    const float* __restrict__ x,
    const float* __restrict__ wq, const float* __restrict__ wk,
    const float* __restrict__ bq, const float* __restrict__ bk,
    __nv_bfloat16* __restrict__ wqk,
    float* __restrict__ bqk, float* __restrict__ ssum4,
    float* __restrict__ rowsum)
{
    const int blk = blockIdx.x;
    const int t = threadIdx.x;

    if (blk < PQ_B) {
        const float qscale = 0.044194173824159216f * 1.4426950408889634f;
        int idx = blk * 256 + t;
        int row = idx >> 9, col = idx & 511;
        int which = row >> 9, rr = row & 511;
        float v = which == 0 ? wq[rr * 512 + col] * qscale : wk[rr * 512 + col];
        wqk[idx] = __float2bfloat16_rn(v);
        if (idx < NQK) {
            int w2 = idx >> 9, r2 = idx & 511;
            bqk[idx] = w2 == 0 ? bq[r2] * qscale : bk[r2];
        }
    } else if (blk < PQ_B + PS_B) {
        const int pb = blk - PQ_B;
        const long long base = (long long)(pb >> 2) * 65536 + (pb & 3) * 16384;
        float s = 0.f, ss = 0.f;
        #pragma unroll 4
        for (int i = t; i < 16384; i += 256) {
            float v = x[base + i];
            s += v; ss += v * v;
        }
        #pragma unroll
        for (int off = 16; off; off >>= 1) {
            s  += __shfl_down_sync(0xffffffffu, s,  off);
            ss += __shfl_down_sync(0xffffffffu, ss, off);
        }
        __shared__ float shs[8], shss[8];
        int wid = t >> 5, lane = t & 31;
        if (lane == 0) { shs[wid] = s; shss[wid] = ss; }
        __syncthreads();
        if (t == 0) {
            float ts = 0.f, tss = 0.f;
            #pragma unroll
            for (int i = 0; i < 8; i++) { ts += shs[i]; tss += shss[i]; }
            ssum4[2 * pb]     = ts;
            ssum4[2 * pb + 1] = tss;
        }
    } else {
        int idx = (blk - PQ_B - PS_B) * 256 + t;
        rowsum[idx] = 0.f;
    }
}

// ---------------------------------------------------------------------------
// GN apply + transpose (bf16 out); sums 4 stat partials inline
// ---------------------------------------------------------------------------
__global__ __launch_bounds__(256) void gn_apply_t_kernel(
    const float* __restrict__ x, const float* __restrict__ w,
    const float* __restrict__ b, const float* __restrict__ ssum4,
    __nv_bfloat16* __restrict__ ht)
{
    __shared__ float tile[32][33];
    const int p0 = blockIdx.x * 32;
    const int c0 = blockIdx.y * 32;
    const int bb = blockIdx.z;
    const int tx = threadIdx.x, ty = threadIdx.y;   // (32, 8)
    const long long xb = (long long)bb * CN;

    #pragma unroll
    for (int r = 0; r < 4; r++) {
        int cl = ty + 8 * r;
        tile[cl][tx] = x[xb + (long long)(c0 + cl) * NPIX + p0 + tx];
    }
    __syncthreads();
    const int c = c0 + tx;
    const int gidx = c >> 4;
    const int bg = bb * 32 + gidx;
    float ts = 0.f, tss = 0.f;
    #pragma unroll
    for (int pp = 0; pp < 4; pp++) {
        ts  += ssum4[2 * (bg * 4 + pp)];
        tss += ssum4[2 * (bg * 4 + pp) + 1];
    }
    const float mean = ts * (1.f / 65536.f);
    const float var  = tss * (1.f / 65536.f) - mean * mean;
    const float rstd = rsqrtf(var + GEPS);
    const float sc = rstd * w[c];
    const float sh = b[c] - mean * sc;
    #pragma unroll
    for (int r = 0; r < 4; r++) {
        int pl = ty + 8 * r;
        float v = tile[tx][pl] * sc + sh;
        ht[xb + (long long)(p0 + pl) * CCH + c] = __float2bfloat16_rn(v);
    }
}

// ---------------------------------------------------------------------------
extern "C" void kernel_launch(void* const* d_in, const int* in_sizes, int n_in,
                              void* d_out, int out_size)
{
    const float* x    = (const float*)d_in[0];
    const float* gn_w = (const float*)d_in[1];
    const float* gn_b = (const float*)d_in[2];
    const float* wq   = (const float*)d_in[3];
    const float* bq   = (const float*)d_in[4];
    const float* wk   = (const float*)d_in[5];
    const float* bk   = (const float*)d_in[6];
    const float* wv   = (const float*)d_in[7];
    const float* bv   = (const float*)d_in[8];
    const float* wo   = (const float*)d_in[9];
    const float* bo   = (const float*)d_in[10];
    float* out = (float*)d_out;

    __nv_bfloat16 *ht, *qk, *v16, *p, *ot, *wqk, *wv16, *wo16;
    float *bqk, *rowsum, *ssum4;
    cudaGetSymbolAddress((void**)&ht,     g_ht);
    cudaGetSymbolAddress((void**)&qk,     g_qk);
    cudaGetSymbolAddress((void**)&v16,    g_v16);
    cudaGetSymbolAddress((void**)&p,      g_p);
    cudaGetSymbolAddress((void**)&ot,     g_ot);
    cudaGetSymbolAddress((void**)&wqk,    g_wqk);
    cudaGetSymbolAddress((void**)&wv16,   g_wv16);
    cudaGetSymbolAddress((void**)&wo16,   g_wo);
    cudaGetSymbolAddress((void**)&bqk,    g_bqk);
    cudaGetSymbolAddress((void**)&rowsum, g_rowsum);
    cudaGetSymbolAddress((void**)&ssum4,  g_ssum4);

    cudaFuncSetAttribute(qk_conv_kernel,
        cudaFuncAttributeMaxDynamicSharedMemorySize, SMEM3);
    cudaFuncSetAttribute(sv_kernel,
        cudaFuncAttributeMaxDynamicSharedMemorySize, SMEM3);
    cudaFuncSetAttribute(gemm_tc<3>,
        cudaFuncAttributeMaxDynamicSharedMemorySize, SMEM3);
    cudaFuncSetAttribute(gemm_tc<4>,
        cudaFuncAttributeMaxDynamicSharedMemorySize, SMEM3);

    // 0) prologue: wqk prep + GN partial stats + rowsum zero
    prologue_kernel<<<PRO_BLOCKS, 256>>>(
        x, wq, wk, bq, bk, wqk, bqk, ssum4, rowsum);

    // 1) GN apply + transpose -> hT bf16 [B][pix][C]
    gn_apply_t_kernel<<<dim3(NPIX / 32, CCH / 32, BATCH), dim3(32, 8)>>>(
        x, gn_w, gn_b, ssum4, ht);

    // 2) qk GEMM (512 CTAs) + wv/wo conversion (2048 tail-filling blocks)
    qk_conv_kernel<<<512 + 2048, 256, SMEM3>>>(
        ht, wqk, qk, bqk, wv, wo, wv16, wo16);

    // 3) fused S + V: 2048 S tiles + 256 V tiles in one launch
    sv_kernel<<<2048 + 256, 256, SMEM3>>>(qk, p, rowsum, wv16, ht, v16, bv);

    // 4) OT[pix][C] = (P @ v16^T) / rowsum[pix]
    dim3 gAV(CCH / BN, NPIX / BM, BATCH);        // 256 CTAs
    gemm_tc<3><<<gAV, 256, SMEM3>>>(
        p, v16, ot, nullptr, rowsum, nullptr,
        NPIX, NPIX, NPIX, CCH, NN, CN, CN, NPIX, 0);

    // 5) out = x + wo @ OT^T + bo[m]  (fp32)
    dim3 gF(NPIX / BN, CCH / BM, BATCH);         // 256 CTAs
    gemm_tc<4><<<gF, 256, SMEM3>>>(
        wo16, ot, out, bo, nullptr, x,
        CCH, CCH, CCH, NPIX, 0, CN, CN, 0, CN);
}

// round 17
// speedup vs baseline: 1.2346x; 1.0011x over previous
#include <cuda_runtime.h>
#include <cuda_bf16.h>
#include <cstdint>

// B=2, C=512, N=4096. out = x + Wo@Attn(GN(x)) + bo, [B,C,H,W] fp32.
// Pipeline: prologue(wqk prep, GN stats, zero) -> gn_apply(hT bf16)
//   -> [qk GEMM + wv/wo bf16 conversion packed] -> [S + V fused] -> AV -> final.
#define BATCH 2
#define CCH   512
#define NPIX  4096
#define NQK   1024
#define GEPS  1e-6f

static const long long CN   = (long long)CCH * NPIX;    // 2M
static const long long NN   = (long long)NPIX * NPIX;   // 16M
static const long long QK2N = (long long)NPIX * NQK;    // 4M

// scratch (device globals)
__device__ __nv_bfloat16 g_ht [BATCH * NPIX * CCH];             // hT [B][pix][C]
__device__ __nv_bfloat16 g_qk [(long long)BATCH * NPIX * NQK];  // [B][pix][q|k]
__device__ __nv_bfloat16 g_v16[BATCH * CCH * NPIX];             // v [B][C][pix]
__device__ __nv_bfloat16 g_p  [(long long)BATCH * NPIX * NPIX]; // exp(S) bf16
__device__ __nv_bfloat16 g_ot [BATCH * NPIX * CCH];             // OT [B][pix][C]
__device__ __nv_bfloat16 g_wqk[NQK * CCH];                      // concat(wq*qs, wk)
__device__ __nv_bfloat16 g_wv16[CCH * CCH];
__device__ __nv_bfloat16 g_wo [CCH * CCH];
__device__ float         g_bqk[NQK];                            // concat(bq*qs, bk)
__device__ float         g_rowsum[BATCH * NPIX];
__device__ float         g_ssum4[BATCH * 32 * 4 * 2];           // GN partials

// ---------------------------------------------------------------------------
// PTX helpers
// ---------------------------------------------------------------------------
__device__ __forceinline__ void cpasync16(uint32_t s, const void* g) {
    asm volatile("cp.async.cg.shared.global [%0], [%1], 16;" :: "r"(s), "l"(g));
}
__device__ __forceinline__ uint32_t smem_u32(const void* p) {
    return (uint32_t)__cvta_generic_to_shared(p);
}
__device__ __forceinline__ void ldsm4(uint32_t r[4], uint32_t addr) {
    asm volatile("ldmatrix.sync.aligned.m8n8.x4.shared.b16 {%0,%1,%2,%3}, [%4];"
        : "=r"(r[0]), "=r"(r[1]), "=r"(r[2]), "=r"(r[3]) : "r"(addr));
}
__device__ __forceinline__ void mma_bf16(float c[4], const uint32_t a[4],
                                         const uint32_t b0, const uint32_t b1) {
    asm volatile(
        "mma.sync.aligned.m16n8k16.row.col.f32.bf16.bf16.f32 "
        "{%0,%1,%2,%3},{%4,%5,%6,%7},{%8,%9},{%0,%1,%2,%3};"
        : "+f"(c[0]), "+f"(c[1]), "+f"(c[2]), "+f"(c[3])
        : "r"(a[0]), "r"(a[1]), "r"(a[2]), "r"(a[3]), "r"(b0), "r"(b1));
}
__device__ __forceinline__ float ex2f(float x) {
    float y; asm("ex2.approx.ftz.f32 %0, %1;" : "=f"(y) : "f"(x));
    return y;
}

// ---------------------------------------------------------------------------
// Shared GEMM core (proven-best config): D[M][N] = A[M][K] * B[N][K]^T
// Block 128x128x64, 256 thr = 8 warps (2x4), warp tile 64x32, m16n8k16,
// 3-stage cp.async, conflict-free 144B-stride smem. All operands NT K-major.
// EPI: 1 = bf16 out + bias[n]   (qk)
//      5 = bf16 out + bias[m]   (v)
//      2 = exp2 + bf16 out + rowsum atomics   (S)
//      3 = bf16 out * (1/rs[m])               (AV)
//      4 = fp32 out + bias[m] + residual      (final)
// ---------------------------------------------------------------------------
#define BM 128
#define BN 128
#define BK 64
#define ASTR 144
#define ASTAGE (BM * ASTR)
#define SMEM3 (6 * ASTAGE)   // 110592

template<int EPI>
__device__ __forceinline__ void gemm_core(
    const __nv_bfloat16* __restrict__ Ab, const __nv_bfloat16* __restrict__ Bb,
    void* __restrict__ Cz,
    const float* __restrict__ bias, float* __restrict__ rsz,
    const float* __restrict__ resz,
    int K, int lda, int ldb, int ldc, int m0, int n0)
{
    extern __shared__ char smem[];
    const uint32_t sbA = smem_u32(smem);
    const uint32_t sbB = sbA + 3 * ASTAGE;

    const int tid  = threadIdx.x;
    const int wid  = tid >> 5;
    const int lane = tid & 31;
    const int g    = lane >> 2;
    const int tig  = lane & 3;
    const int sub  = lane >> 3;
    const int r8   = lane & 7;
    const int m_w  = (wid >> 2) * 64;
    const int n_w  = (wid & 3) * 32;

    const __nv_bfloat16* Abt = Ab + (long long)m0 * lda;
    const __nv_bfloat16* Bbt = Bb + (long long)n0 * ldb;

    float acc[4][4][4];
    #pragma unroll
    for (int i = 0; i < 4; i++)
        #pragma unroll
        for (int j = 0; j < 4; j++)
            #pragma unroll
            for (int r = 0; r < 4; r++) acc[i][j][r] = 0.f;

    const int nk = K / BK;

    auto load = [&](int ks, int buf) {
        const uint32_t ab = sbA + buf * ASTAGE;
        const uint32_t bb = sbB + buf * ASTAGE;
        #pragma unroll
        for (int it = 0; it < 4; it++) {
            int s = tid + it * 256;
            int r = s >> 3, c = s & 7;
            cpasync16(ab + r * ASTR + c * 16,
                      Abt + (long long)r * lda + ks * BK + c * 8);
        }
        #pragma unroll
        for (int it = 0; it < 4; it++) {
            int s = tid + it * 256;
            int r = s >> 3, c = s & 7;
            cpasync16(bb + r * ASTR + c * 16,
                      Bbt + (long long)r * ldb + ks * BK + c * 8);
        }
        asm volatile("cp.async.commit_group;");
    };

    load(0, 0);
    if (nk > 1) load(1, 1);

    #pragma unroll 1
    for (int ks = 0; ks < nk; ks++) {
        const int buf = ks % 3;
        if (ks + 1 < nk) asm volatile("cp.async.wait_group 1;");
        else             asm volatile("cp.async.wait_group 0;");
        __syncthreads();
        if (ks + 2 < nk) load(ks + 2, (ks + 2) % 3);

        const uint32_t ab = sbA + buf * ASTAGE;
        const uint32_t bb = sbB + buf * ASTAGE;

        #pragma unroll
        for (int kk = 0; kk < 4; kk++) {
            uint32_t af[4][4];
            #pragma unroll
            for (int i = 0; i < 4; i++) {
                uint32_t addr = ab + (m_w + 16 * i + (sub & 1) * 8 + r8) * ASTR
                              + kk * 32 + (sub >> 1) * 16;
                ldsm4(af[i], addr);
            }
            uint32_t bf[4][2];
            #pragma unroll
            for (int jj = 0; jj < 2; jj++) {
                uint32_t t[4];
                uint32_t addr = bb + (n_w + 16 * jj + (sub >> 1) * 8 + r8) * ASTR
                              + kk * 32 + (sub & 1) * 16;
                ldsm4(t, addr);
                bf[2 * jj][0] = t[0]; bf[2 * jj][1] = t[1];
                bf[2 * jj + 1][0] = t[2]; bf[2 * jj + 1][1] = t[3];
            }
            #pragma unroll
            for (int i = 0; i < 4; i++)
                #pragma unroll
                for (int j = 0; j < 4; j++)
                    mma_bf16(acc[i][j], af[i], bf[j][0], bf[j][1]);
        }
    }

    // ------------------------------ epilogues ------------------------------
    if (EPI == 1) {
        __nv_bfloat16* C = (__nv_bfloat16*)Cz;
        #pragma unroll
        for (int i = 0; i < 4; i++) {
            int r0 = m0 + m_w + 16 * i + g, r1 = r0 + 8;
            #pragma unroll
            for (int j = 0; j < 4; j++) {
                int col = n0 + n_w + 8 * j + 2 * tig;
                float bn0 = bias[col], bn1 = bias[col + 1];
                *(__nv_bfloat162*)&C[(long long)r0 * ldc + col] =
                    __float22bfloat162_rn(make_float2(acc[i][j][0] + bn0,
                                                      acc[i][j][1] + bn1));
                *(__nv_bfloat162*)&C[(long long)r1 * ldc + col] =
                    __float22bfloat162_rn(make_float2(acc[i][j][2] + bn0,
                                                      acc[i][j][3] + bn1));
            }
        }
    } else if (EPI == 5) {
        __nv_bfloat16* C = (__nv_bfloat16*)Cz;
        #pragma unroll
        for (int i = 0; i < 4; i++) {
            int r0 = m0 + m_w + 16 * i + g, r1 = r0 + 8;
            float bm0 = bias[r0], bm1 = bias[r1];
            #pragma unroll
            for (int j = 0; j < 4; j++) {
                int col = n0 + n_w + 8 * j + 2 * tig;
                *(__nv_bfloat162*)&C[(long long)r0 * ldc + col] =
                    __float22bfloat162_rn(make_float2(acc[i][j][0] + bm0,
                                                      acc[i][j][1] + bm0));
                *(__nv_bfloat162*)&C[(long long)r1 * ldc + col] =
                    __float22bfloat162_rn(make_float2(acc[i][j][2] + bm1,
                                                      acc[i][j][3] + bm1));
            }
        }
    } else if (EPI == 2) {
        __nv_bfloat16* C = (__nv_bfloat16*)Cz;
        #pragma unroll
        for (int i = 0; i < 4; i++) {
            int r0 = m0 + m_w + 16 * i + g, r1 = r0 + 8;
            float s0 = 0.f, s1 = 0.f;
            #pragma unroll
            for (int j = 0; j < 4; j++) {
                int col = n0 + n_w + 8 * j + 2 * tig;
                float e0 = ex2f(acc[i][j][0]);
                float e1 = ex2f(acc[i][j][1]);
                float e2 = ex2f(acc[i][j][2]);
                float e3 = ex2f(acc[i][j][3]);
                s0 += e0 + e1; s1 += e2 + e3;
                *(__nv_bfloat162*)&C[(long long)r0 * ldc + col] =
                    __float22bfloat162_rn(make_float2(e0, e1));
                *(__nv_bfloat162*)&C[(long long)r1 * ldc + col] =
                    __float22bfloat162_rn(make_float2(e2, e3));
            }
            s0 += __shfl_xor_sync(0xffffffffu, s0, 1);
            s0 += __shfl_xor_sync(0xffffffffu, s0, 2);
            s1 += __shfl_xor_sync(0xffffffffu, s1, 1);
            s1 += __shfl_xor_sync(0xffffffffu, s1, 2);
            if (tig == 0) {
                atomicAdd(&rsz[r0], s0);
                atomicAdd(&rsz[r1], s1);
            }
        }
    } else if (EPI == 3) {
        __nv_bfloat16* C = (__nv_bfloat16*)Cz;
        #pragma unroll
        for (int i = 0; i < 4; i++) {
            int r0 = m0 + m_w + 16 * i + g, r1 = r0 + 8;
            float i0 = 1.f / rsz[r0];
            float i1 = 1.f / rsz[r1];
            #pragma unroll
            for (int j = 0; j < 4; j++) {
                int col = n0 + n_w + 8 * j + 2 * tig;
                *(__nv_bfloat162*)&C[(long long)r0 * ldc + col] =
                    __float22bfloat162_rn(make_float2(acc[i][j][0] * i0,
                                                      acc[i][j][1] * i0));
                *(__nv_bfloat162*)&C[(long long)r1 * ldc + col] =
                    __float22bfloat162_rn(make_float2(acc[i][j][2] * i1,
                                                      acc[i][j][3] * i1));
            }
        }
    } else {
        float* C = (float*)Cz;
        #pragma unroll
        for (int i = 0; i < 4; i++) {
            int r0 = m0 + m_w + 16 * i + g, r1 = r0 + 8;
            float bm0 = bias[r0], bm1 = bias[r1];
            #pragma unroll
            for (int j = 0; j < 4; j++) {
                int col = n0 + n_w + 8 * j + 2 * tig;
                long long o0 = (long long)r0 * ldc + col;
                long long o1 = (long long)r1 * ldc + col;
                float2 a0 = *(const float2*)&resz[o0];
                float2 a1 = *(const float2*)&resz[o1];
                float2 v0 = make_float2(acc[i][j][0] + bm0 + a0.x,
                                        acc[i][j][1] + bm0 + a0.y);
                float2 v1 = make_float2(acc[i][j][2] + bm1 + a1.x,
                                        acc[i][j][3] + bm1 + a1.y);
                *(float2*)&C[o0] = v0;
                *(float2*)&C[o1] = v1;
            }
        }
    }
}

// Plain GEMM launcher (AV / final)
template<int EPI>
__global__ __launch_bounds__(256, 2) void gemm_tc(
    const __nv_bfloat16* __restrict__ A, const __nv_bfloat16* __restrict__ B,
    void* __restrict__ Cv,
    const float* __restrict__ bias, float* __restrict__ aux,
    const float* __restrict__ res,
    int K, int lda, int ldb, int ldc,
    long long sA, long long sB, long long sC, long long sAux, long long sR)
{
    const int z = blockIdx.z;
    gemm_core<EPI>(
        A + (long long)z * sA, B + (long long)z * sB,
        (char*)Cv + (long long)z * sC * (EPI == 4 ? 4 : 2),
        bias, aux ? aux + (long long)z * sAux : nullptr,
        res ? res + (long long)z * sR : nullptr,
        K, lda, ldb, ldc, blockIdx.y * BM, blockIdx.x * BN);
}

// qk GEMM (512 CTAs) + wv/wo bf16 conversion (512 micro-blocks: 256 each).
// Each conversion block handles 256 threads x 4 elems = 1024 elems;
// 256 blocks x 1024 = 262144 = CCH*CCH exactly (bounds-exact).
__global__ __launch_bounds__(256, 2) void qk_conv_kernel(
    const __nv_bfloat16* __restrict__ ht, const __nv_bfloat16* __restrict__ wqk,
    __nv_bfloat16* __restrict__ qk, const float* __restrict__ bqk,
    const float* __restrict__ wv, const float* __restrict__ wo,
    __nv_bfloat16* __restrict__ wv16, __nv_bfloat16* __restrict__ wo16)
{
    const int idx = blockIdx.x;
    if (idx < 512) {
        // qk: [pix][1024] = ht @ wqk^T + bqk[n];  M=4096, N=1024, K=512
        const int b = idx >> 8, r = idx & 255;
        const int m0 = (r >> 3) * BM, n0 = (r & 7) * BN;
        gemm_core<1>(ht + (long long)b * CN, wqk,
                     qk + (long long)b * QK2N,
                     bqk, nullptr, nullptr,
                     CCH, CCH, CCH, NQK, m0, n0);
    } else {
        // fp32 -> bf16 weight conversion
        const int t = idx - 512;                       // 0..511
        const int base = (t & 255) * 256 + (int)threadIdx.x;  // float4 index
        const float* src = (t < 256) ? wv : wo;
        __nv_bfloat16* dst = (t < 256) ? wv16 : wo16;
        float4 v = *(const float4*)&src[base * 4];
        *(__nv_bfloat162*)&dst[base * 4] =
            __float22bfloat162_rn(make_float2(v.x, v.y));
        *(__nv_bfloat162*)&dst[base * 4 + 2] =
            __float22bfloat162_rn(make_float2(v.z, v.w));
    }
}

// Fused S + V launch: blocks [0,2048) = S tiles, [2048,2304) = V tiles.
__global__ __launch_bounds__(256, 2) void sv_kernel(
    const __nv_bfloat16* __restrict__ qk, __nv_bfloat16* __restrict__ p,
    float* __restrict__ rowsum,
    const __nv_bfloat16* __restrict__ wv16, const __nv_bfloat16* __restrict__ ht,
    __nv_bfloat16* __restrict__ v16, const float* __restrict__ bv)
{
    const int idx = blockIdx.x;
    if (idx < 2048) {
        const int b = idx >> 10, r = idx & 1023;
        const int m0 = ((r >> 5) & 31) * BM, n0 = (r & 31) * BN;
        const __nv_bfloat16* qkz = qk + (long long)b * QK2N;
        gemm_core<2>(qkz, qkz + 512, p + (long long)b * NN,
                     nullptr, rowsum + (long long)b * NPIX, nullptr,
                     CCH, NQK, NQK, NPIX, m0, n0);
    } else {
        const int t = idx - 2048;
        const int b = t >> 7, r = t & 127;
        const int m0 = ((r >> 5) & 3) * BM, n0 = (r & 31) * BN;
        gemm_core<5>(wv16, ht + (long long)b * CN, v16 + (long long)b * CN,
                     bv, nullptr, nullptr,
                     CCH, CCH, CCH, NPIX, m0, n0);
    }
}

// ---------------------------------------------------------------------------
// Prologue: [0,2048) wqk prep | [2048,2304) GN partial stats | [2304,2336) zero
// ---------------------------------------------------------------------------
#define PQ_B 2048
#define PS_B 256
#define PZ_B 32
#define PRO_BLOCKS (PQ_B + PS_B + PZ_B)

__global__ __launch_bounds__(256) void prologue_kernel(
    const float* __restrict__ x,
    const float* __restrict__ wq, const float* __restrict__ wk,
    const float* __restrict__ bq, const float* __restrict__ bk,
    __nv_bfloat16* __restrict__ wqk,
    float* __restrict__ bqk, float* __restrict__ ssum4,
    float* __restrict__ rowsum)
{
    const int blk = blockIdx.x;
    const int t = threadIdx.x;

    if (blk < PQ_B) {
        const float qscale = 0.044194173824159216f * 1.4426950408889634f;
        int idx = blk * 256 + t;
        int row = idx >> 9, col = idx & 511;
        int which = row >> 9, rr = row & 511;
        float v = which == 0 ? wq[rr * 512 + col] * qscale : wk[rr * 512 + col];
        wqk[idx] = __float2bfloat16_rn(v);
        if (idx < NQK) {
            int w2 = idx >> 9, r2 = idx & 511;
            bqk[idx] = w2 == 0 ? bq[r2] * qscale : bk[r2];
        }
    } else if (blk < PQ_B + PS_B) {
        const int pb = blk - PQ_B;
        const long long base = (long long)(pb >> 2) * 65536 + (pb & 3) * 16384;
        float s = 0.f, ss = 0.f;
        #pragma unroll 4
        for (int i = t; i < 16384; i += 256) {
            float v = x[base + i];
            s += v; ss += v * v;
        }
        #pragma unroll
        for (int off = 16; off; off >>= 1) {
            s  += __shfl_down_sync(0xffffffffu, s,  off);
            ss += __shfl_down_sync(0xffffffffu, ss, off);
        }
        __shared__ float shs[8], shss[8];
        int wid = t >> 5, lane = t & 31;
        if (lane == 0) { shs[wid] = s; shss[wid] = ss; }
        __syncthreads();
        if (t == 0) {
            float ts = 0.f, tss = 0.f;
            #pragma unroll
            for (int i = 0; i < 8; i++) { ts += shs[i]; tss += shss[i]; }
            ssum4[2 * pb]     = ts;
            ssum4[2 * pb + 1] = tss;
        }
    } else {
        int idx = (blk - PQ_B - PS_B) * 256 + t;
        rowsum[idx] = 0.f;
    }
}

// ---------------------------------------------------------------------------
// GN apply + transpose (bf16 out); sums 4 stat partials inline
// ---------------------------------------------------------------------------
__global__ __launch_bounds__(256) void gn_apply_t_kernel(
    const float* __restrict__ x, const float* __restrict__ w,
    const float* __restrict__ b, const float* __restrict__ ssum4,
    __nv_bfloat16* __restrict__ ht)
{
    __shared__ float tile[32][33];
    const int p0 = blockIdx.x * 32;
    const int c0 = blockIdx.y * 32;
    const int bb = blockIdx.z;
    const int tx = threadIdx.x, ty = threadIdx.y;   // (32, 8)
    const long long xb = (long long)bb * CN;

    #pragma unroll
    for (int r = 0; r < 4; r++) {
        int cl = ty + 8 * r;
        tile[cl][tx] = x[xb + (long long)(c0 + cl) * NPIX + p0 + tx];
    }
    __syncthreads();
    const int c = c0 + tx;
    const int gidx = c >> 4;
    const int bg = bb * 32 + gidx;
    float ts = 0.f, tss = 0.f;
    #pragma unroll
    for (int pp = 0; pp < 4; pp++) {
        ts  += ssum4[2 * (bg * 4 + pp)];
        tss += ssum4[2 * (bg * 4 + pp) + 1];
    }
    const float mean = ts * (1.f / 65536.f);
    const float var  = tss * (1.f / 65536.f) - mean * mean;
    const float rstd = rsqrtf(var + GEPS);
    const float sc = rstd * w[c];
    const float sh = b[c] - mean * sc;
    #pragma unroll
    for (int r = 0; r < 4; r++) {
        int pl = ty + 8 * r;
        float v = tile[tx][pl] * sc + sh;
        ht[xb + (long long)(p0 + pl) * CCH + c] = __float2bfloat16_rn(v);
    }
}

// ---------------------------------------------------------------------------
extern "C" void kernel_launch(void* const* d_in, const int* in_sizes, int n_in,
                              void* d_out, int out_size)
{
    const float* x    = (const float*)d_in[0];
    const float* gn_w = (const float*)d_in[1];
    const float* gn_b = (const float*)d_in[2];
    const float* wq   = (const float*)d_in[3];
    const float* bq   = (const float*)d_in[4];
    const float* wk   = (const float*)d_in[5];
    const float* bk   = (const float*)d_in[6];
    const float* wv   = (const float*)d_in[7];
    const float* bv   = (const float*)d_in[8];
    const float* wo   = (const float*)d_in[9];
    const float* bo   = (const float*)d_in[10];
    float* out = (float*)d_out;

    __nv_bfloat16 *ht, *qk, *v16, *p, *ot, *wqk, *wv16, *wo16;
    float *bqk, *rowsum, *ssum4;
    cudaGetSymbolAddress((void**)&ht,     g_ht);
    cudaGetSymbolAddress((void**)&qk,     g_qk);
    cudaGetSymbolAddress((void**)&v16,    g_v16);
    cudaGetSymbolAddress((void**)&p,      g_p);
    cudaGetSymbolAddress((void**)&ot,     g_ot);
    cudaGetSymbolAddress((void**)&wqk,    g_wqk);
    cudaGetSymbolAddress((void**)&wv16,   g_wv16);
    cudaGetSymbolAddress((void**)&wo16,   g_wo);
    cudaGetSymbolAddress((void**)&bqk,    g_bqk);
    cudaGetSymbolAddress((void**)&rowsum, g_rowsum);
    cudaGetSymbolAddress((void**)&ssum4,  g_ssum4);

    cudaFuncSetAttribute(qk_conv_kernel,
        cudaFuncAttributeMaxDynamicSharedMemorySize, SMEM3);
    cudaFuncSetAttribute(sv_kernel,
        cudaFuncAttributeMaxDynamicSharedMemorySize, SMEM3);
    cudaFuncSetAttribute(gemm_tc<3>,
        cudaFuncAttributeMaxDynamicSharedMemorySize, SMEM3);
    cudaFuncSetAttribute(gemm_tc<4>,
        cudaFuncAttributeMaxDynamicSharedMemorySize, SMEM3);

    // 0) prologue: wqk prep + GN partial stats + rowsum zero
    prologue_kernel<<<PRO_BLOCKS, 256>>>(
        x, wq, wk, bq, bk, wqk, bqk, ssum4, rowsum);

    // 1) GN apply + transpose -> hT bf16 [B][pix][C]
    gn_apply_t_kernel<<<dim3(NPIX / 32, CCH / 32, BATCH), dim3(32, 8)>>>(
        x, gn_w, gn_b, ssum4, ht);

    // 2) qk GEMM (512 CTAs) + wv/wo conversion (512 bounds-exact blocks)
    qk_conv_kernel<<<512 + 512, 256, SMEM3>>>(
        ht, wqk, qk, bqk, wv, wo, wv16, wo16);

    // 3) fused S + V: 2048 S tiles + 256 V tiles in one launch
    sv_kernel<<<2048 + 256, 256, SMEM3>>>(qk, p, rowsum, wv16, ht, v16, bv);

    // 4) OT[pix][C] = (P @ v16^T) / rowsum[pix]
    dim3 gAV(CCH / BN, NPIX / BM, BATCH);        // 256 CTAs
    gemm_tc<3><<<gAV, 256, SMEM3>>>(
        p, v16, ot, nullptr, rowsum, nullptr,
        NPIX, NPIX, NPIX, CCH, NN, CN, CN, NPIX, 0);

    // 5) out = x + wo @ OT^T + bo[m]  (fp32)
    dim3 gF(NPIX / BN, CCH / BM, BATCH);         // 256 CTAs
    gemm_tc<4><<<gF, 256, SMEM3>>>(
        wo16, ot, out, bo, nullptr, x,
        CCH, CCH, CCH, NPIX, 0, CN, CN, 0, CN);
}